// round 3
// baseline (speedup 1.0000x reference)
#include <cuda_runtime.h>
#include <cstdint>

#define BATCH  8
#define SEQ    2048
#define DMODEL 512
#define NHEAD  8
#define DHEAD  64
#define ROWS   (BATCH * SEQ)     // 16384
#define QKVDIM (3 * DMODEL)      // 1536

// Scratch (allocation-free contract: __device__ globals)
__device__ float g_xn [ROWS * DMODEL];   // 32 MB
__device__ float g_qkv[ROWS * QKVDIM];   // 96 MB
__device__ float g_att[ROWS * DMODEL];   // 32 MB

// ---------------------------------------------------------------------------
// helpers: tf32 convert + m16n8k8 tf32 mma
// ---------------------------------------------------------------------------
__device__ __forceinline__ uint32_t f2tf(float x) {
    uint32_t r;
    asm("cvt.rna.tf32.f32 %0, %1;" : "=r"(r) : "f"(x));
    return r;
}

__device__ __forceinline__ void mma8(float& c0, float& c1, float& c2, float& c3,
                                     uint32_t a0, uint32_t a1, uint32_t a2, uint32_t a3,
                                     uint32_t b0, uint32_t b1) {
    asm volatile(
        "mma.sync.aligned.m16n8k8.row.col.f32.tf32.tf32.f32 "
        "{%0,%1,%2,%3}, {%4,%5,%6,%7}, {%8,%9}, {%0,%1,%2,%3};"
        : "+f"(c0), "+f"(c1), "+f"(c2), "+f"(c3)
        : "r"(a0), "r"(a1), "r"(a2), "r"(a3), "r"(b0), "r"(b1));
}

// ---------------------------------------------------------------------------
// LayerNorm: one block (128 threads) per row of 512
// ---------------------------------------------------------------------------
__global__ __launch_bounds__(128) void ln_kernel(
    const float* __restrict__ x, const float* __restrict__ gamma,
    const float* __restrict__ beta, float* __restrict__ out)
{
    int row = blockIdx.x;
    int t   = threadIdx.x;
    const float* xr = x + (size_t)row * DMODEL;
    float4 v = *(const float4*)(xr + t * 4);
    float s  = v.x + v.y + v.z + v.w;
    float ss = v.x * v.x + v.y * v.y + v.z * v.z + v.w * v.w;
#pragma unroll
    for (int m = 16; m; m >>= 1) {
        s  += __shfl_xor_sync(0xffffffffu, s,  m);
        ss += __shfl_xor_sync(0xffffffffu, ss, m);
    }
    __shared__ float red[8];
    if ((t & 31) == 0) { red[t >> 5] = s; red[4 + (t >> 5)] = ss; }
    __syncthreads();
    float tot  = red[0] + red[1] + red[2] + red[3];
    float tot2 = red[4] + red[5] + red[6] + red[7];
    float mu   = tot * (1.0f / DMODEL);
    float var  = tot2 * (1.0f / DMODEL) - mu * mu;
    float rstd = rsqrtf(var + 1e-6f);
    float4 g = *(const float4*)(gamma + t * 4);
    float4 b = *(const float4*)(beta  + t * 4);
    float4 o;
    o.x = (v.x - mu) * rstd * g.x + b.x;
    o.y = (v.y - mu) * rstd * g.y + b.y;
    o.z = (v.z - mu) * rstd * g.z + b.z;
    o.w = (v.w - mu) * rstd * g.w + b.w;
    *(float4*)(out + (size_t)row * DMODEL + t * 4) = o;
}

// ---------------------------------------------------------------------------
// tf32 tensor-core GEMM (NT): C[M,N] = A[M,K=512] * B[N,K=512]^T (+bias)
// CTA tile 128x128x16, 8 warps (2m x 4n), warp tile 64x32.
// Smem holds PRE-CONVERTED tf32 bits, columns pair-permuted inside each
// 8-k group (k -> 2*(k%4)+(k/4)) so fragment pairs are single LDS.64.
// Double-buffered: one __syncthreads per k-tile.
// ---------------------------------------------------------------------------
#define GK 512
#define GS 20   // smem row stride (uint32)

template <bool BIAS>
__global__ __launch_bounds__(256, 2) void mm_tf32(
    const float* __restrict__ A, const float* __restrict__ Bw,
    const float* __restrict__ bias, float* __restrict__ C, int N)
{
    __shared__ uint32_t As[2][128][GS];
    __shared__ uint32_t Bs[2][128][GS];
    int t    = threadIdx.x;
    int m0   = blockIdx.y * 128, n0 = blockIdx.x * 128;
    int warp = t >> 5, lane = t & 31, g = lane >> 2, tq = lane & 3;
    int wm   = (warp >> 2) * 64, wn = (warp & 3) * 32;

    int lrow = t >> 2;        // 0..63 (and +64)
    int lk4  = t & 3;         // which float4 within the 16-k tile
    // permuted store columns: element i of the float4 goes to cbase + 2*i
    int cbase = (lk4 >> 1) * 8 + (lk4 & 1);
    const float* Ag = A  + (size_t)(m0 + lrow) * GK + lk4 * 4;
    const float* Bg = Bw + (size_t)(n0 + lrow) * GK + lk4 * 4;

    float acc[4][4][4];
#pragma unroll
    for (int i = 0; i < 4; i++)
#pragma unroll
        for (int j = 0; j < 4; j++)
#pragma unroll
            for (int r = 0; r < 4; r++) acc[i][j][r] = 0.f;

    float4 ra0 = *(const float4*)Ag;
    float4 ra1 = *(const float4*)(Ag + (size_t)64 * GK);
    float4 rb0 = *(const float4*)Bg;
    float4 rb1 = *(const float4*)(Bg + (size_t)64 * GK);

#define STASH(buf)                                                           \
    do {                                                                     \
        As[buf][lrow][cbase + 0] = f2tf(ra0.x);                              \
        As[buf][lrow][cbase + 2] = f2tf(ra0.y);                              \
        As[buf][lrow][cbase + 4] = f2tf(ra0.z);                              \
        As[buf][lrow][cbase + 6] = f2tf(ra0.w);                              \
        As[buf][lrow + 64][cbase + 0] = f2tf(ra1.x);                         \
        As[buf][lrow + 64][cbase + 2] = f2tf(ra1.y);                         \
        As[buf][lrow + 64][cbase + 4] = f2tf(ra1.z);                         \
        As[buf][lrow + 64][cbase + 6] = f2tf(ra1.w);                         \
        Bs[buf][lrow][cbase + 0] = f2tf(rb0.x);                              \
        Bs[buf][lrow][cbase + 2] = f2tf(rb0.y);                              \
        Bs[buf][lrow][cbase + 4] = f2tf(rb0.z);                              \
        Bs[buf][lrow][cbase + 6] = f2tf(rb0.w);                              \
        Bs[buf][lrow + 64][cbase + 0] = f2tf(rb1.x);                         \
        Bs[buf][lrow + 64][cbase + 2] = f2tf(rb1.y);                         \
        Bs[buf][lrow + 64][cbase + 4] = f2tf(rb1.z);                         \
        Bs[buf][lrow + 64][cbase + 6] = f2tf(rb1.w);                         \
    } while (0)

    STASH(0);
    __syncthreads();

    const int NT = GK / 16;
    for (int kt = 0; kt < NT; kt++) {
        int buf = kt & 1;
        if (kt + 1 < NT) {
            ra0 = *(const float4*)(Ag + (kt + 1) * 16);
            ra1 = *(const float4*)(Ag + (size_t)64 * GK + (kt + 1) * 16);
            rb0 = *(const float4*)(Bg + (kt + 1) * 16);
            rb1 = *(const float4*)(Bg + (size_t)64 * GK + (kt + 1) * 16);
        }
#pragma unroll
        for (int ks = 0; ks < 2; ks++) {
            int kc = ks * 8 + 2 * tq;
            uint2 a0[4], a1[4], bf[4];
#pragma unroll
            for (int mt = 0; mt < 4; mt++) {
                a0[mt] = *(const uint2*)&As[buf][wm + mt * 16 + g][kc];
                a1[mt] = *(const uint2*)&As[buf][wm + mt * 16 + 8 + g][kc];
            }
#pragma unroll
            for (int nt = 0; nt < 4; nt++)
                bf[nt] = *(const uint2*)&Bs[buf][wn + nt * 8 + g][kc];
#pragma unroll
            for (int mt = 0; mt < 4; mt++)
#pragma unroll
                for (int nt = 0; nt < 4; nt++)
                    mma8(acc[mt][nt][0], acc[mt][nt][1], acc[mt][nt][2], acc[mt][nt][3],
                         a0[mt].x, a1[mt].x, a0[mt].y, a1[mt].y,
                         bf[nt].x, bf[nt].y);
        }
        if (kt + 1 < NT) STASH(buf ^ 1);
        __syncthreads();
    }
#undef STASH

#pragma unroll
    for (int mt = 0; mt < 4; mt++) {
#pragma unroll
        for (int nt = 0; nt < 4; nt++) {
            int row = m0 + wm + mt * 16 + g;
            int col = n0 + wn + nt * 8 + 2 * tq;
            float b0 = 0.f, b1 = 0.f;
            if (BIAS) { b0 = bias[col]; b1 = bias[col + 1]; }
            float2 v0 = make_float2(acc[mt][nt][0] + b0, acc[mt][nt][1] + b1);
            float2 v1 = make_float2(acc[mt][nt][2] + b0, acc[mt][nt][3] + b1);
            *(float2*)(C + (size_t)row * N + col)       = v0;
            *(float2*)(C + (size_t)(row + 8) * N + col) = v1;
        }
    }
}

// ---------------------------------------------------------------------------
// Flash attention, tf32 tensor cores.
// CTA = 128 Q rows of one (b,h); 8 warps x 16 rows; 64-key chunks.
// K stored key-major, V stored TRANSPOSED (d-major); both pre-converted to
// tf32 with pair-permuted columns -> all B-fragment loads are LDS.64.
// P parked in warp-private slab pre-converted + permuted -> LDS.64 reloads.
// 2 CTAs/SM.
// ---------------------------------------------------------------------------
#define QS 68   // Q/P slab stride (floats)
#define KVS 66  // K/V stride (uint32)
#define ATTN_SMEM_FLOATS (128 * QS + 2 * 64 * KVS)

__global__ __launch_bounds__(256, 2) void attn_tf32(
    const float* __restrict__ qkv, float* __restrict__ out)
{
    extern __shared__ float sm[];
    float*    QP = sm;                               // [128][QS]
    uint32_t* Ks = (uint32_t*)(sm + 128 * QS);       // [64][KVS] key-major
    uint32_t* Vs = Ks + 64 * KVS;                    // [64][KVS] d-major (V^T)

    int t = threadIdx.x, warp = t >> 5, lane = t & 31, g = lane >> 2, tq = lane & 3;
    int bh = blockIdx.y, b = bh >> 3, h = bh & 7;
    int mb = blockIdx.x * 128;
    size_t seq0 = (size_t)b * SEQ;
    const float* base  = qkv + seq0 * QKVDIM + h * DHEAD;
    const float* kbase = base + DMODEL;
    const float* vbase = base + 2 * DMODEL;

    int d4 = t & 15, r0 = t >> 4;
    // permuted col base for K staging (cols cb + 2*i), i = element of float4
    int kcb = (d4 >> 1) * 8 + (d4 & 1);

    // Stage Q tile (coalesced fp32), then per-warp Q fragments (scaled).
    {
#pragma unroll
        for (int j = 0; j < 8; j++) {
            int row = r0 + 16 * j;
            *(float4*)&QP[row * QS + d4 * 4] =
                *(const float4*)(base + (size_t)(mb + row) * QKVDIM + d4 * 4);
        }
    }
    __syncthreads();

    uint32_t qf[8][4];
    float*    Pw  = QP + warp * 16 * QS;   // warp-private 16-row slab
    uint32_t* Pwu = (uint32_t*)Pw;
    {
        const float scale = 0.125f;    // 1/sqrt(64)
#pragma unroll
        for (int ks = 0; ks < 8; ks++) {
            qf[ks][0] = f2tf(Pw[g * QS + ks * 8 + tq] * scale);
            qf[ks][1] = f2tf(Pw[(g + 8) * QS + ks * 8 + tq] * scale);
            qf[ks][2] = f2tf(Pw[g * QS + ks * 8 + tq + 4] * scale);
            qf[ks][3] = f2tf(Pw[(g + 8) * QS + ks * 8 + tq + 4] * scale);
        }
    }

    float oacc[8][4];
#pragma unroll
    for (int nt = 0; nt < 8; nt++)
#pragma unroll
        for (int r = 0; r < 4; r++) oacc[nt][r] = 0.f;
    float M0 = -1e30f, M1 = -1e30f, L0 = 0.f, L1 = 0.f;

    // P write columns (permuted): c0 for even key 2tq, c0+2 for 2tq+1
    int pc0 = 4 * (tq & 1) + (tq >> 1);

    for (int kc = 0; kc < SEQ / 64; kc++) {
        __syncthreads();   // previous QK/PV reads of Ks/Vs complete
        {
#pragma unroll
            for (int j = 0; j < 4; j++) {
                int row = r0 + 16 * j;
                size_t key = (size_t)(kc * 64 + row);
                // K: key-major, d permuted
                float4 kv = *(const float4*)(kbase + key * QKVDIM + d4 * 4);
                uint32_t* kr = Ks + row * KVS;
                kr[kcb + 0] = f2tf(kv.x);
                kr[kcb + 2] = f2tf(kv.y);
                kr[kcb + 4] = f2tf(kv.z);
                kr[kcb + 6] = f2tf(kv.w);
                // V: transposed (d-major), key permuted
                float4 vv = *(const float4*)(vbase + key * QKVDIM + d4 * 4);
                int vc = (row >> 3) * 8 + 2 * (row & 3) + ((row & 7) >> 2);
                Vs[(d4 * 4 + 0) * KVS + vc] = f2tf(vv.x);
                Vs[(d4 * 4 + 1) * KVS + vc] = f2tf(vv.y);
                Vs[(d4 * 4 + 2) * KVS + vc] = f2tf(vv.z);
                Vs[(d4 * 4 + 3) * KVS + vc] = f2tf(vv.w);
            }
        }
        __syncthreads();

        // S = (Q*scale) K^T : nt = key group, ks = d group
        float sacc[8][4];
#pragma unroll
        for (int nt = 0; nt < 8; nt++)
#pragma unroll
            for (int r = 0; r < 4; r++) sacc[nt][r] = 0.f;

#pragma unroll
        for (int ks = 0; ks < 8; ks++) {
            int kcol = ks * 8 + 2 * tq;
#pragma unroll
            for (int nt = 0; nt < 8; nt++) {
                uint2 bf = *(const uint2*)&Ks[(nt * 8 + g) * KVS + kcol];
                mma8(sacc[nt][0], sacc[nt][1], sacc[nt][2], sacc[nt][3],
                     qf[ks][0], qf[ks][1], qf[ks][2], qf[ks][3], bf.x, bf.y);
            }
        }

        // Online softmax (row = 4 lanes: xor 1,2)
        float cm0 = sacc[0][0], cm1 = sacc[0][2];
#pragma unroll
        for (int nt = 0; nt < 8; nt++) {
            cm0 = fmaxf(cm0, fmaxf(sacc[nt][0], sacc[nt][1]));
            cm1 = fmaxf(cm1, fmaxf(sacc[nt][2], sacc[nt][3]));
        }
        cm0 = fmaxf(cm0, __shfl_xor_sync(0xffffffffu, cm0, 1));
        cm0 = fmaxf(cm0, __shfl_xor_sync(0xffffffffu, cm0, 2));
        cm1 = fmaxf(cm1, __shfl_xor_sync(0xffffffffu, cm1, 1));
        cm1 = fmaxf(cm1, __shfl_xor_sync(0xffffffffu, cm1, 2));
        float nM0 = fmaxf(M0, cm0), nM1 = fmaxf(M1, cm1);
        float a0 = __expf(M0 - nM0), a1 = __expf(M1 - nM1);
        float rs0 = 0.f, rs1 = 0.f;
#pragma unroll
        for (int nt = 0; nt < 8; nt++) {
            sacc[nt][0] = __expf(sacc[nt][0] - nM0);
            sacc[nt][1] = __expf(sacc[nt][1] - nM0);
            sacc[nt][2] = __expf(sacc[nt][2] - nM1);
            sacc[nt][3] = __expf(sacc[nt][3] - nM1);
            rs0 += sacc[nt][0] + sacc[nt][1];
            rs1 += sacc[nt][2] + sacc[nt][3];
        }
        rs0 += __shfl_xor_sync(0xffffffffu, rs0, 1);
        rs0 += __shfl_xor_sync(0xffffffffu, rs0, 2);
        rs1 += __shfl_xor_sync(0xffffffffu, rs1, 1);
        rs1 += __shfl_xor_sync(0xffffffffu, rs1, 2);
        L0 = L0 * a0 + rs0;  M0 = nM0;
        L1 = L1 * a1 + rs1;  M1 = nM1;

        // Rescale O; park P pre-converted + key-permuted in warp slab
#pragma unroll
        for (int nt = 0; nt < 8; nt++) {
            oacc[nt][0] *= a0; oacc[nt][1] *= a0;
            oacc[nt][2] *= a1; oacc[nt][3] *= a1;
            int c = nt * 8 + pc0;
            Pwu[g * QS + c]            = f2tf(sacc[nt][0]);
            Pwu[g * QS + c + 2]        = f2tf(sacc[nt][1]);
            Pwu[(g + 8) * QS + c]      = f2tf(sacc[nt][2]);
            Pwu[(g + 8) * QS + c + 2]  = f2tf(sacc[nt][3]);
        }
        __syncwarp();

        // O += P @ V : ks = key group, nt = d group
#pragma unroll
        for (int ks = 0; ks < 8; ks++) {
            int kcol = ks * 8 + 2 * tq;
            uint2 p0 = *(const uint2*)&Pwu[g * QS + kcol];
            uint2 p1 = *(const uint2*)&Pwu[(g + 8) * QS + kcol];
#pragma unroll
            for (int nt = 0; nt < 8; nt++) {
                uint2 bf = *(const uint2*)&Vs[(nt * 8 + g) * KVS + kcol];
                mma8(oacc[nt][0], oacc[nt][1], oacc[nt][2], oacc[nt][3],
                     p0.x, p1.x, p0.y, p1.y, bf.x, bf.y);
            }
        }
    }

    // Normalize, write out[b, n, h*64 + d]
    float i0 = 1.0f / L0, i1 = 1.0f / L1;
    int row0 = mb + warp * 16 + g;
#pragma unroll
    for (int nt = 0; nt < 8; nt++) {
        int col = h * DHEAD + nt * 8 + 2 * tq;
        *(float2*)(out + (seq0 + row0) * DMODEL + col) =
            make_float2(oacc[nt][0] * i0, oacc[nt][1] * i0);
        *(float2*)(out + (seq0 + row0 + 8) * DMODEL + col) =
            make_float2(oacc[nt][2] * i1, oacc[nt][3] * i1);
    }
}

// ---------------------------------------------------------------------------
extern "C" void kernel_launch(void* const* d_in, const int* in_sizes, int n_in,
                              void* d_out, int out_size)
{
    (void)in_sizes; (void)n_in; (void)out_size;
    const float* x      = (const float*)d_in[0];
    const float* w_qkv  = (const float*)d_in[1];
    const float* w_proj = (const float*)d_in[2];
    const float* b_proj = (const float*)d_in[3];
    const float* gamma  = (const float*)d_in[4];
    const float* beta   = (const float*)d_in[5];
    float* out = (float*)d_out;

    float *xn, *qkvp, *att;
    cudaGetSymbolAddress((void**)&xn,   g_xn);
    cudaGetSymbolAddress((void**)&qkvp, g_qkv);
    cudaGetSymbolAddress((void**)&att,  g_att);

    const int SMEM = ATTN_SMEM_FLOATS * (int)sizeof(float);
    cudaFuncSetAttribute(attn_tf32,
                         cudaFuncAttributeMaxDynamicSharedMemorySize, SMEM);

    ln_kernel<<<ROWS, 128>>>(x, gamma, beta, xn);
    mm_tf32<false><<<dim3(QKVDIM / 128, ROWS / 128), 256>>>(
        xn, w_qkv, nullptr, qkvp, QKVDIM);
    attn_tf32<<<dim3(SEQ / 128, BATCH * NHEAD), 256, SMEM>>>(qkvp, att);
    mm_tf32<true><<<dim3(DMODEL / 128, ROWS / 128), 256>>>(
        att, w_proj, b_proj, out, DMODEL);
}

// round 4
// speedup vs baseline: 1.5279x; 1.5279x over previous
#include <cuda_runtime.h>
#include <cstdint>

#define BATCH  8
#define SEQ    2048
#define DMODEL 512
#define NHEAD  8
#define DHEAD  64
#define ROWS   (BATCH * SEQ)     // 16384
#define QKVDIM (3 * DMODEL)      // 1536

// Scratch (allocation-free contract: __device__ globals)
__device__ float g_xn [ROWS * DMODEL];   // 32 MB
__device__ float g_qkv[ROWS * QKVDIM];   // 96 MB
__device__ float g_att[ROWS * DMODEL];   // 32 MB

// ---------------------------------------------------------------------------
// helpers: tf32 convert + m16n8k8 tf32 mma
// ---------------------------------------------------------------------------
__device__ __forceinline__ uint32_t f2tf(float x) {
    uint32_t r;
    asm("cvt.rna.tf32.f32 %0, %1;" : "=r"(r) : "f"(x));
    return r;
}

__device__ __forceinline__ void mma8(float& c0, float& c1, float& c2, float& c3,
                                     uint32_t a0, uint32_t a1, uint32_t a2, uint32_t a3,
                                     uint32_t b0, uint32_t b1) {
    asm volatile(
        "mma.sync.aligned.m16n8k8.row.col.f32.tf32.tf32.f32 "
        "{%0,%1,%2,%3}, {%4,%5,%6,%7}, {%8,%9}, {%0,%1,%2,%3};"
        : "+f"(c0), "+f"(c1), "+f"(c2), "+f"(c3)
        : "r"(a0), "r"(a1), "r"(a2), "r"(a3), "r"(b0), "r"(b1));
}

// ---------------------------------------------------------------------------
// LayerNorm: one block (128 threads) per row of 512
// ---------------------------------------------------------------------------
__global__ __launch_bounds__(128) void ln_kernel(
    const float* __restrict__ x, const float* __restrict__ gamma,
    const float* __restrict__ beta, float* __restrict__ out)
{
    int row = blockIdx.x;
    int t   = threadIdx.x;
    const float* xr = x + (size_t)row * DMODEL;
    float4 v = *(const float4*)(xr + t * 4);
    float s  = v.x + v.y + v.z + v.w;
    float ss = v.x * v.x + v.y * v.y + v.z * v.z + v.w * v.w;
#pragma unroll
    for (int m = 16; m; m >>= 1) {
        s  += __shfl_xor_sync(0xffffffffu, s,  m);
        ss += __shfl_xor_sync(0xffffffffu, ss, m);
    }
    __shared__ float red[8];
    if ((t & 31) == 0) { red[t >> 5] = s; red[4 + (t >> 5)] = ss; }
    __syncthreads();
    float tot  = red[0] + red[1] + red[2] + red[3];
    float tot2 = red[4] + red[5] + red[6] + red[7];
    float mu   = tot * (1.0f / DMODEL);
    float var  = tot2 * (1.0f / DMODEL) - mu * mu;
    float rstd = rsqrtf(var + 1e-6f);
    float4 g = *(const float4*)(gamma + t * 4);
    float4 b = *(const float4*)(beta  + t * 4);
    float4 o;
    o.x = (v.x - mu) * rstd * g.x + b.x;
    o.y = (v.y - mu) * rstd * g.y + b.y;
    o.z = (v.z - mu) * rstd * g.z + b.z;
    o.w = (v.w - mu) * rstd * g.w + b.w;
    *(float4*)(out + (size_t)row * DMODEL + t * 4) = o;
}

// ---------------------------------------------------------------------------
// tf32 tensor-core GEMM (NT): C[M,N] = A[M,K=512] * B[N,K=512]^T (+bias)
// CTA tile 128x128x16, 8 warps (2m x 4n), warp tile 64x32.
// Same layout/addressing as the measured 1047us version, EXCEPT smem holds
// pre-converted tf32 bits (vectorized STS.128 of converted values) so the
// inner loop has no CVTs. Scalar fragment LDS are bank-conflict-free.
// ---------------------------------------------------------------------------
#define GK 512
#define GS 20   // smem row stride (uint32)

template <bool BIAS>
__global__ __launch_bounds__(256, 2) void mm_tf32(
    const float* __restrict__ A, const float* __restrict__ Bw,
    const float* __restrict__ bias, float* __restrict__ C, int N)
{
    __shared__ uint32_t As[128][GS];
    __shared__ uint32_t Bs[128][GS];
    int t    = threadIdx.x;
    int m0   = blockIdx.y * 128, n0 = blockIdx.x * 128;
    int warp = t >> 5, lane = t & 31, g = lane >> 2, tq = lane & 3;
    int wm   = (warp >> 2) * 64, wn = (warp & 3) * 32;

    int lrow = t >> 2;        // 0..63 (and +64)
    int lk4  = t & 3;         // which float4 within the 16-k tile
    const float* Ag = A  + (size_t)(m0 + lrow) * GK + lk4 * 4;
    const float* Bg = Bw + (size_t)(n0 + lrow) * GK + lk4 * 4;

    float acc[4][4][4];
#pragma unroll
    for (int i = 0; i < 4; i++)
#pragma unroll
        for (int j = 0; j < 4; j++)
#pragma unroll
            for (int r = 0; r < 4; r++) acc[i][j][r] = 0.f;

    float4 ra0 = *(const float4*)Ag;
    float4 ra1 = *(const float4*)(Ag + (size_t)64 * GK);
    float4 rb0 = *(const float4*)Bg;
    float4 rb1 = *(const float4*)(Bg + (size_t)64 * GK);

    const int NT = GK / 16;
    for (int kt = 0; kt < NT; kt++) {
        *(uint4*)&As[lrow][lk4 * 4] =
            make_uint4(f2tf(ra0.x), f2tf(ra0.y), f2tf(ra0.z), f2tf(ra0.w));
        *(uint4*)&As[lrow + 64][lk4 * 4] =
            make_uint4(f2tf(ra1.x), f2tf(ra1.y), f2tf(ra1.z), f2tf(ra1.w));
        *(uint4*)&Bs[lrow][lk4 * 4] =
            make_uint4(f2tf(rb0.x), f2tf(rb0.y), f2tf(rb0.z), f2tf(rb0.w));
        *(uint4*)&Bs[lrow + 64][lk4 * 4] =
            make_uint4(f2tf(rb1.x), f2tf(rb1.y), f2tf(rb1.z), f2tf(rb1.w));
        __syncthreads();
        if (kt + 1 < NT) {
            ra0 = *(const float4*)(Ag + (kt + 1) * 16);
            ra1 = *(const float4*)(Ag + (size_t)64 * GK + (kt + 1) * 16);
            rb0 = *(const float4*)(Bg + (kt + 1) * 16);
            rb1 = *(const float4*)(Bg + (size_t)64 * GK + (kt + 1) * 16);
        }
#pragma unroll
        for (int ks = 0; ks < 2; ks++) {
            int k0 = ks * 8;
            uint32_t af[4][4], bf[4][2];
#pragma unroll
            for (int mt = 0; mt < 4; mt++) {
                int r = wm + mt * 16 + g;
                af[mt][0] = As[r][k0 + tq];
                af[mt][1] = As[r + 8][k0 + tq];
                af[mt][2] = As[r][k0 + tq + 4];
                af[mt][3] = As[r + 8][k0 + tq + 4];
            }
#pragma unroll
            for (int nt = 0; nt < 4; nt++) {
                int r = wn + nt * 8 + g;
                bf[nt][0] = Bs[r][k0 + tq];
                bf[nt][1] = Bs[r][k0 + tq + 4];
            }
#pragma unroll
            for (int mt = 0; mt < 4; mt++)
#pragma unroll
                for (int nt = 0; nt < 4; nt++)
                    mma8(acc[mt][nt][0], acc[mt][nt][1], acc[mt][nt][2], acc[mt][nt][3],
                         af[mt][0], af[mt][1], af[mt][2], af[mt][3],
                         bf[nt][0], bf[nt][1]);
        }
        __syncthreads();
    }

#pragma unroll
    for (int mt = 0; mt < 4; mt++) {
#pragma unroll
        for (int nt = 0; nt < 4; nt++) {
            int row = m0 + wm + mt * 16 + g;
            int col = n0 + wn + nt * 8 + 2 * tq;
            float b0 = 0.f, b1 = 0.f;
            if (BIAS) { b0 = bias[col]; b1 = bias[col + 1]; }
            float2 v0 = make_float2(acc[mt][nt][0] + b0, acc[mt][nt][1] + b1);
            float2 v1 = make_float2(acc[mt][nt][2] + b0, acc[mt][nt][3] + b1);
            *(float2*)(C + (size_t)row * N + col)       = v0;
            *(float2*)(C + (size_t)(row + 8) * N + col) = v1;
        }
    }
}

// ---------------------------------------------------------------------------
// Flash attention, tf32 tensor cores.
// CTA = 128 Q rows of one (b,h); 8 warps x 16 rows; 64-key chunks.
// Layout identical to the measured 1047us version (fp32 in smem, in-loop
// cvt), but K/V smem is DOUBLE-BUFFERED with a distance-2 LDG pipeline:
// one __syncthreads per chunk, global-load latency hidden under compute.
// 1 CTA/SM, no register cap (no spills).
// ---------------------------------------------------------------------------
#define AS 68   // attn smem stride (floats)
#define ATTN_SMEM_FLOATS (128 * AS + 4 * 64 * AS)

__global__ __launch_bounds__(256, 1) void attn_tf32(
    const float* __restrict__ qkv, float* __restrict__ out)
{
    extern __shared__ float sm[];
    float* QP = sm;                        // [128][AS] Q stage, then P slabs
    float* Ks = sm + 128 * AS;             // [2][64][AS] key-major
    float* Vs = Ks + 2 * 64 * AS;          // [2][64][AS] key-major

    int t = threadIdx.x, warp = t >> 5, lane = t & 31, g = lane >> 2, tq = lane & 3;
    int bh = blockIdx.y, b = bh >> 3, h = bh & 7;
    int mb = blockIdx.x * 128;
    size_t seq0 = (size_t)b * SEQ;
    const float* base  = qkv + seq0 * QKVDIM + h * DHEAD;
    const float* kbase = base + DMODEL;
    const float* vbase = base + 2 * DMODEL;

    int d4 = t & 15, r0 = t >> 4;

    // Stage Q tile (coalesced), then per-warp Q fragments (scaled).
    {
#pragma unroll
        for (int j = 0; j < 8; j++) {
            int row = r0 + 16 * j;
            *(float4*)&QP[row * AS + d4 * 4] =
                *(const float4*)(base + (size_t)(mb + row) * QKVDIM + d4 * 4);
        }
    }
    __syncthreads();

    uint32_t qf[8][4];
    float* Pw = QP + warp * 16 * AS;   // warp-private 16-row slab
    {
        const float scale = 0.125f;    // 1/sqrt(64)
#pragma unroll
        for (int ks = 0; ks < 8; ks++) {
            qf[ks][0] = f2tf(Pw[g * AS + ks * 8 + tq] * scale);
            qf[ks][1] = f2tf(Pw[(g + 8) * AS + ks * 8 + tq] * scale);
            qf[ks][2] = f2tf(Pw[g * AS + ks * 8 + tq + 4] * scale);
            qf[ks][3] = f2tf(Pw[(g + 8) * AS + ks * 8 + tq + 4] * scale);
        }
    }

    float oacc[8][4];
#pragma unroll
    for (int nt = 0; nt < 8; nt++)
#pragma unroll
        for (int r = 0; r < 4; r++) oacc[nt][r] = 0.f;
    float M0 = -1e30f, M1 = -1e30f, L0 = 0.f, L1 = 0.f;

    const int NC = SEQ / 64;
    float4 kreg[4], vreg[4];

    // LDG of chunk c into registers
#define LDG_CHUNK(c)                                                          \
    do {                                                                      \
        size_t key = (size_t)((c) * 64 + r0);                                 \
        _Pragma("unroll")                                                     \
        for (int j = 0; j < 4; j++) {                                         \
            kreg[j] = *(const float4*)(kbase + (key + 16 * j) * QKVDIM + d4 * 4); \
            vreg[j] = *(const float4*)(vbase + (key + 16 * j) * QKVDIM + d4 * 4); \
        }                                                                     \
    } while (0)

    // STS of held registers into buffer p
#define STS_CHUNK(p)                                                          \
    do {                                                                      \
        float* kb = Ks + (p) * 64 * AS;                                       \
        float* vb = Vs + (p) * 64 * AS;                                       \
        _Pragma("unroll")                                                     \
        for (int j = 0; j < 4; j++) {                                         \
            int row = r0 + 16 * j;                                            \
            *(float4*)&kb[row * AS + d4 * 4] = kreg[j];                       \
            *(float4*)&vb[row * AS + d4 * 4] = vreg[j];                       \
        }                                                                     \
    } while (0)

    LDG_CHUNK(0);
    STS_CHUNK(0);
    LDG_CHUNK(1);
    __syncthreads();

    for (int kc = 0; kc < NC; kc++) {
        int p = kc & 1;
        if (kc + 1 < NC) STS_CHUNK(p ^ 1);
        if (kc + 2 < NC) LDG_CHUNK(kc + 2);
        const float* Kb = Ks + p * 64 * AS;
        const float* Vb = Vs + p * 64 * AS;

        // S = (Q*scale) K^T : nt = key group, ks = d group
        float sacc[8][4];
#pragma unroll
        for (int nt = 0; nt < 8; nt++)
#pragma unroll
            for (int r = 0; r < 4; r++) sacc[nt][r] = 0.f;

#pragma unroll
        for (int ks = 0; ks < 8; ks++) {
            int k0 = ks * 8;
#pragma unroll
            for (int nt = 0; nt < 8; nt++) {
                int kr = nt * 8 + g;
                uint32_t b0 = f2tf(Kb[kr * AS + k0 + tq]);
                uint32_t b1 = f2tf(Kb[kr * AS + k0 + tq + 4]);
                mma8(sacc[nt][0], sacc[nt][1], sacc[nt][2], sacc[nt][3],
                     qf[ks][0], qf[ks][1], qf[ks][2], qf[ks][3], b0, b1);
            }
        }

        // Online softmax (row = 4 lanes: xor 1,2)
        float cm0 = sacc[0][0], cm1 = sacc[0][2];
#pragma unroll
        for (int nt = 0; nt < 8; nt++) {
            cm0 = fmaxf(cm0, fmaxf(sacc[nt][0], sacc[nt][1]));
            cm1 = fmaxf(cm1, fmaxf(sacc[nt][2], sacc[nt][3]));
        }
        cm0 = fmaxf(cm0, __shfl_xor_sync(0xffffffffu, cm0, 1));
        cm0 = fmaxf(cm0, __shfl_xor_sync(0xffffffffu, cm0, 2));
        cm1 = fmaxf(cm1, __shfl_xor_sync(0xffffffffu, cm1, 1));
        cm1 = fmaxf(cm1, __shfl_xor_sync(0xffffffffu, cm1, 2));
        float nM0 = fmaxf(M0, cm0), nM1 = fmaxf(M1, cm1);
        float a0 = __expf(M0 - nM0), a1 = __expf(M1 - nM1);
        float rs0 = 0.f, rs1 = 0.f;
#pragma unroll
        for (int nt = 0; nt < 8; nt++) {
            sacc[nt][0] = __expf(sacc[nt][0] - nM0);
            sacc[nt][1] = __expf(sacc[nt][1] - nM0);
            sacc[nt][2] = __expf(sacc[nt][2] - nM1);
            sacc[nt][3] = __expf(sacc[nt][3] - nM1);
            rs0 += sacc[nt][0] + sacc[nt][1];
            rs1 += sacc[nt][2] + sacc[nt][3];
        }
        rs0 += __shfl_xor_sync(0xffffffffu, rs0, 1);
        rs0 += __shfl_xor_sync(0xffffffffu, rs0, 2);
        rs1 += __shfl_xor_sync(0xffffffffu, rs1, 1);
        rs1 += __shfl_xor_sync(0xffffffffu, rs1, 2);
        L0 = L0 * a0 + rs0;  M0 = nM0;
        L1 = L1 * a1 + rs1;  M1 = nM1;

        // Rescale O; park P in the warp-private smem slab (C-layout)
#pragma unroll
        for (int nt = 0; nt < 8; nt++) {
            oacc[nt][0] *= a0; oacc[nt][1] *= a0;
            oacc[nt][2] *= a1; oacc[nt][3] *= a1;
            *(float2*)&Pw[g * AS + nt * 8 + 2 * tq] =
                make_float2(sacc[nt][0], sacc[nt][1]);
            *(float2*)&Pw[(g + 8) * AS + nt * 8 + 2 * tq] =
                make_float2(sacc[nt][2], sacc[nt][3]);
        }
        __syncwarp();

        // O += P @ V
#pragma unroll
        for (int ks = 0; ks < 8; ks++) {
            int k0 = ks * 8;
            uint32_t pa0 = f2tf(Pw[g * AS + k0 + tq]);
            uint32_t pa1 = f2tf(Pw[(g + 8) * AS + k0 + tq]);
            uint32_t pa2 = f2tf(Pw[g * AS + k0 + tq + 4]);
            uint32_t pa3 = f2tf(Pw[(g + 8) * AS + k0 + tq + 4]);
#pragma unroll
            for (int nt = 0; nt < 8; nt++) {
                uint32_t b0 = f2tf(Vb[(k0 + tq) * AS + nt * 8 + g]);
                uint32_t b1 = f2tf(Vb[(k0 + tq + 4) * AS + nt * 8 + g]);
                mma8(oacc[nt][0], oacc[nt][1], oacc[nt][2], oacc[nt][3],
                     pa0, pa1, pa2, pa3, b0, b1);
            }
        }
        __syncthreads();   // all warps done reading buf p; next iter may STS it
    }
#undef LDG_CHUNK
#undef STS_CHUNK

    // Normalize, write out[b, n, h*64 + d]
    float i0 = 1.0f / L0, i1 = 1.0f / L1;
    int row0 = mb + warp * 16 + g;
#pragma unroll
    for (int nt = 0; nt < 8; nt++) {
        int col = h * DHEAD + nt * 8 + 2 * tq;
        *(float2*)(out + (seq0 + row0) * DMODEL + col) =
            make_float2(oacc[nt][0] * i0, oacc[nt][1] * i0);
        *(float2*)(out + (seq0 + row0 + 8) * DMODEL + col) =
            make_float2(oacc[nt][2] * i1, oacc[nt][3] * i1);
    }
}

// ---------------------------------------------------------------------------
extern "C" void kernel_launch(void* const* d_in, const int* in_sizes, int n_in,
                              void* d_out, int out_size)
{
    (void)in_sizes; (void)n_in; (void)out_size;
    const float* x      = (const float*)d_in[0];
    const float* w_qkv  = (const float*)d_in[1];
    const float* w_proj = (const float*)d_in[2];
    const float* b_proj = (const float*)d_in[3];
    const float* gamma  = (const float*)d_in[4];
    const float* beta   = (const float*)d_in[5];
    float* out = (float*)d_out;

    float *xn, *qkvp, *att;
    cudaGetSymbolAddress((void**)&xn,   g_xn);
    cudaGetSymbolAddress((void**)&qkvp, g_qkv);
    cudaGetSymbolAddress((void**)&att,  g_att);

    const int SMEM = ATTN_SMEM_FLOATS * (int)sizeof(float);
    cudaFuncSetAttribute(attn_tf32,
                         cudaFuncAttributeMaxDynamicSharedMemorySize, SMEM);

    ln_kernel<<<ROWS, 128>>>(x, gamma, beta, xn);
    mm_tf32<false><<<dim3(QKVDIM / 128, ROWS / 128), 256>>>(
        xn, w_qkv, nullptr, qkvp, QKVDIM);
    attn_tf32<<<dim3(SEQ / 128, BATCH * NHEAD), 256, SMEM>>>(qkvp, att);
    mm_tf32<true><<<dim3(DMODEL / 128, ROWS / 128), 256>>>(
        att, w_proj, b_proj, out, DMODEL);
}

// round 5
// speedup vs baseline: 1.5359x; 1.0052x over previous
#include <cuda_runtime.h>
#include <cstdint>

#define BATCH  8
#define SEQ    2048
#define DMODEL 512
#define NHEAD  8
#define DHEAD  64
#define ROWS   (BATCH * SEQ)     // 16384
#define QKVDIM (3 * DMODEL)      // 1536

// Scratch (allocation-free contract: __device__ globals)
__device__ float g_xn [ROWS * DMODEL];   // 32 MB
__device__ float g_qkv[ROWS * QKVDIM];   // 96 MB
__device__ float g_att[ROWS * DMODEL];   // 32 MB

// ---------------------------------------------------------------------------
// helpers: tf32 convert + m16n8k8 tf32 mma
// ---------------------------------------------------------------------------
__device__ __forceinline__ uint32_t f2tf(float x) {
    uint32_t r;
    asm("cvt.rna.tf32.f32 %0, %1;" : "=r"(r) : "f"(x));
    return r;
}

__device__ __forceinline__ void mma8(float& c0, float& c1, float& c2, float& c3,
                                     uint32_t a0, uint32_t a1, uint32_t a2, uint32_t a3,
                                     uint32_t b0, uint32_t b1) {
    asm volatile(
        "mma.sync.aligned.m16n8k8.row.col.f32.tf32.tf32.f32 "
        "{%0,%1,%2,%3}, {%4,%5,%6,%7}, {%8,%9}, {%0,%1,%2,%3};"
        : "+f"(c0), "+f"(c1), "+f"(c2), "+f"(c3)
        : "r"(a0), "r"(a1), "r"(a2), "r"(a3), "r"(b0), "r"(b1));
}

// ---------------------------------------------------------------------------
// LayerNorm: one block (128 threads) per row of 512
// ---------------------------------------------------------------------------
__global__ __launch_bounds__(128) void ln_kernel(
    const float* __restrict__ x, const float* __restrict__ gamma,
    const float* __restrict__ beta, float* __restrict__ out)
{
    int row = blockIdx.x;
    int t   = threadIdx.x;
    const float* xr = x + (size_t)row * DMODEL;
    float4 v = *(const float4*)(xr + t * 4);
    float s  = v.x + v.y + v.z + v.w;
    float ss = v.x * v.x + v.y * v.y + v.z * v.z + v.w * v.w;
#pragma unroll
    for (int m = 16; m; m >>= 1) {
        s  += __shfl_xor_sync(0xffffffffu, s,  m);
        ss += __shfl_xor_sync(0xffffffffu, ss, m);
    }
    __shared__ float red[8];
    if ((t & 31) == 0) { red[t >> 5] = s; red[4 + (t >> 5)] = ss; }
    __syncthreads();
    float tot  = red[0] + red[1] + red[2] + red[3];
    float tot2 = red[4] + red[5] + red[6] + red[7];
    float mu   = tot * (1.0f / DMODEL);
    float var  = tot2 * (1.0f / DMODEL) - mu * mu;
    float rstd = rsqrtf(var + 1e-6f);
    float4 g = *(const float4*)(gamma + t * 4);
    float4 b = *(const float4*)(beta  + t * 4);
    float4 o;
    o.x = (v.x - mu) * rstd * g.x + b.x;
    o.y = (v.y - mu) * rstd * g.y + b.y;
    o.z = (v.z - mu) * rstd * g.z + b.z;
    o.w = (v.w - mu) * rstd * g.w + b.w;
    *(float4*)(out + (size_t)row * DMODEL + t * 4) = o;
}

// ---------------------------------------------------------------------------
// tf32 tensor-core GEMM (NT): C[M,N] = A[M,K=512] * B[N,K=512]^T (+bias)
// (unchanged from measured-best R4 version)
// ---------------------------------------------------------------------------
#define GK 512
#define GS 20   // smem row stride (uint32)

template <bool BIAS>
__global__ __launch_bounds__(256, 2) void mm_tf32(
    const float* __restrict__ A, const float* __restrict__ Bw,
    const float* __restrict__ bias, float* __restrict__ C, int N)
{
    __shared__ uint32_t As[128][GS];
    __shared__ uint32_t Bs[128][GS];
    int t    = threadIdx.x;
    int m0   = blockIdx.y * 128, n0 = blockIdx.x * 128;
    int warp = t >> 5, lane = t & 31, g = lane >> 2, tq = lane & 3;
    int wm   = (warp >> 2) * 64, wn = (warp & 3) * 32;

    int lrow = t >> 2;        // 0..63 (and +64)
    int lk4  = t & 3;         // which float4 within the 16-k tile
    const float* Ag = A  + (size_t)(m0 + lrow) * GK + lk4 * 4;
    const float* Bg = Bw + (size_t)(n0 + lrow) * GK + lk4 * 4;

    float acc[4][4][4];
#pragma unroll
    for (int i = 0; i < 4; i++)
#pragma unroll
        for (int j = 0; j < 4; j++)
#pragma unroll
            for (int r = 0; r < 4; r++) acc[i][j][r] = 0.f;

    float4 ra0 = *(const float4*)Ag;
    float4 ra1 = *(const float4*)(Ag + (size_t)64 * GK);
    float4 rb0 = *(const float4*)Bg;
    float4 rb1 = *(const float4*)(Bg + (size_t)64 * GK);

    const int NT = GK / 16;
    for (int kt = 0; kt < NT; kt++) {
        *(uint4*)&As[lrow][lk4 * 4] =
            make_uint4(f2tf(ra0.x), f2tf(ra0.y), f2tf(ra0.z), f2tf(ra0.w));
        *(uint4*)&As[lrow + 64][lk4 * 4] =
            make_uint4(f2tf(ra1.x), f2tf(ra1.y), f2tf(ra1.z), f2tf(ra1.w));
        *(uint4*)&Bs[lrow][lk4 * 4] =
            make_uint4(f2tf(rb0.x), f2tf(rb0.y), f2tf(rb0.z), f2tf(rb0.w));
        *(uint4*)&Bs[lrow + 64][lk4 * 4] =
            make_uint4(f2tf(rb1.x), f2tf(rb1.y), f2tf(rb1.z), f2tf(rb1.w));
        __syncthreads();
        if (kt + 1 < NT) {
            ra0 = *(const float4*)(Ag + (kt + 1) * 16);
            ra1 = *(const float4*)(Ag + (size_t)64 * GK + (kt + 1) * 16);
            rb0 = *(const float4*)(Bg + (kt + 1) * 16);
            rb1 = *(const float4*)(Bg + (size_t)64 * GK + (kt + 1) * 16);
        }
#pragma unroll
        for (int ks = 0; ks < 2; ks++) {
            int k0 = ks * 8;
            uint32_t af[4][4], bf[4][2];
#pragma unroll
            for (int mt = 0; mt < 4; mt++) {
                int r = wm + mt * 16 + g;
                af[mt][0] = As[r][k0 + tq];
                af[mt][1] = As[r + 8][k0 + tq];
                af[mt][2] = As[r][k0 + tq + 4];
                af[mt][3] = As[r + 8][k0 + tq + 4];
            }
#pragma unroll
            for (int nt = 0; nt < 4; nt++) {
                int r = wn + nt * 8 + g;
                bf[nt][0] = Bs[r][k0 + tq];
                bf[nt][1] = Bs[r][k0 + tq + 4];
            }
#pragma unroll
            for (int mt = 0; mt < 4; mt++)
#pragma unroll
                for (int nt = 0; nt < 4; nt++)
                    mma8(acc[mt][nt][0], acc[mt][nt][1], acc[mt][nt][2], acc[mt][nt][3],
                         af[mt][0], af[mt][1], af[mt][2], af[mt][3],
                         bf[nt][0], bf[nt][1]);
        }
        __syncthreads();
    }

#pragma unroll
    for (int mt = 0; mt < 4; mt++) {
#pragma unroll
        for (int nt = 0; nt < 4; nt++) {
            int row = m0 + wm + mt * 16 + g;
            int col = n0 + wn + nt * 8 + 2 * tq;
            float b0 = 0.f, b1 = 0.f;
            if (BIAS) { b0 = bias[col]; b1 = bias[col + 1]; }
            float2 v0 = make_float2(acc[mt][nt][0] + b0, acc[mt][nt][1] + b1);
            float2 v1 = make_float2(acc[mt][nt][2] + b0, acc[mt][nt][3] + b1);
            *(float2*)(C + (size_t)row * N + col)       = v0;
            *(float2*)(C + (size_t)(row + 8) * N + col) = v1;
        }
    }
}

// ---------------------------------------------------------------------------
// Flash attention, tf32 tensor cores.
// CTA = 256 Q rows of one (b,h); 512 threads = 16 warps x 16 rows.
// K/V smem double-buffered, stored as PRE-CONVERTED tf32 bits in the same
// key-major layout (vectorized uint4 STS) -> no cvt in the MMA loops.
// Prefetch LDG placed between QK and PV so kreg/vreg are not live across
// the register-peak QK loop (512 thr => 128-reg cap).
// ---------------------------------------------------------------------------
#define AS 68   // attn smem stride (words)
#define AROWS 256
#define ATTN_SMEM_FLOATS (AROWS * AS + 4 * 64 * AS)   // 139264 bytes

__global__ __launch_bounds__(512, 1) void attn_tf32(
    const float* __restrict__ qkv, float* __restrict__ out)
{
    extern __shared__ float sm[];
    float*    QP = sm;                           // [256][AS] Q stage, P slabs
    uint32_t* Ks = (uint32_t*)(sm + AROWS * AS); // [2][64][AS] key-major tf32
    uint32_t* Vs = Ks + 2 * 64 * AS;             // [2][64][AS] key-major tf32

    int t = threadIdx.x, warp = t >> 5, lane = t & 31, g = lane >> 2, tq = lane & 3;
    int bh = blockIdx.y, b = bh >> 3, h = bh & 7;
    int mb = blockIdx.x * AROWS;
    size_t seq0 = (size_t)b * SEQ;
    const float* base  = qkv + seq0 * QKVDIM + h * DHEAD;
    const float* kbase = base + DMODEL;
    const float* vbase = base + 2 * DMODEL;

    int d4 = t & 15, r0 = t >> 4;   // r0: 0..31

    // Stage Q tile (coalesced), then per-warp Q fragments (scaled).
    {
#pragma unroll
        for (int j = 0; j < 8; j++) {
            int row = r0 + 32 * j;
            *(float4*)&QP[row * AS + d4 * 4] =
                *(const float4*)(base + (size_t)(mb + row) * QKVDIM + d4 * 4);
        }
    }
    __syncthreads();

    uint32_t qf[8][4];
    float* Pw = QP + warp * 16 * AS;   // warp-private 16-row slab
    {
        const float scale = 0.125f;    // 1/sqrt(64)
#pragma unroll
        for (int ks = 0; ks < 8; ks++) {
            qf[ks][0] = f2tf(Pw[g * AS + ks * 8 + tq] * scale);
            qf[ks][1] = f2tf(Pw[(g + 8) * AS + ks * 8 + tq] * scale);
            qf[ks][2] = f2tf(Pw[g * AS + ks * 8 + tq + 4] * scale);
            qf[ks][3] = f2tf(Pw[(g + 8) * AS + ks * 8 + tq + 4] * scale);
        }
    }

    float oacc[8][4];
#pragma unroll
    for (int nt = 0; nt < 8; nt++)
#pragma unroll
        for (int r = 0; r < 4; r++) oacc[nt][r] = 0.f;
    float M0 = -1e30f, M1 = -1e30f, L0 = 0.f, L1 = 0.f;

    const int NC = SEQ / 64;
    float4 kreg[2], vreg[2];

    // LDG of chunk c into registers (rows r0, r0+32)
#define LDG_CHUNK(c)                                                          \
    do {                                                                      \
        size_t key = (size_t)((c) * 64 + r0);                                 \
        _Pragma("unroll")                                                     \
        for (int j = 0; j < 2; j++) {                                         \
            kreg[j] = *(const float4*)(kbase + (key + 32 * j) * QKVDIM + d4 * 4); \
            vreg[j] = *(const float4*)(vbase + (key + 32 * j) * QKVDIM + d4 * 4); \
        }                                                                     \
    } while (0)

    // STS of held registers into buffer p, converted to tf32 bits
#define STS_CHUNK(p)                                                          \
    do {                                                                      \
        uint32_t* kb = Ks + (p) * 64 * AS;                                    \
        uint32_t* vb = Vs + (p) * 64 * AS;                                    \
        _Pragma("unroll")                                                     \
        for (int j = 0; j < 2; j++) {                                         \
            int row = r0 + 32 * j;                                            \
            *(uint4*)&kb[row * AS + d4 * 4] = make_uint4(                     \
                f2tf(kreg[j].x), f2tf(kreg[j].y), f2tf(kreg[j].z), f2tf(kreg[j].w)); \
            *(uint4*)&vb[row * AS + d4 * 4] = make_uint4(                     \
                f2tf(vreg[j].x), f2tf(vreg[j].y), f2tf(vreg[j].z), f2tf(vreg[j].w)); \
        }                                                                     \
    } while (0)

    LDG_CHUNK(0);
    STS_CHUNK(0);
    LDG_CHUNK(1);
    __syncthreads();

    for (int kc = 0; kc < NC; kc++) {
        int p = kc & 1;
        if (kc + 1 < NC) STS_CHUNK(p ^ 1);   // consumes kreg/vreg
        const uint32_t* Kb = Ks + p * 64 * AS;
        const uint32_t* Vb = Vs + p * 64 * AS;

        // S = (Q*scale) K^T : nt = key group, ks = d group
        float sacc[8][4];
#pragma unroll
        for (int nt = 0; nt < 8; nt++)
#pragma unroll
            for (int r = 0; r < 4; r++) sacc[nt][r] = 0.f;

#pragma unroll
        for (int ks = 0; ks < 8; ks++) {
            int k0 = ks * 8;
#pragma unroll
            for (int nt = 0; nt < 8; nt++) {
                int kr = nt * 8 + g;
                uint32_t b0 = Kb[kr * AS + k0 + tq];
                uint32_t b1 = Kb[kr * AS + k0 + tq + 4];
                mma8(sacc[nt][0], sacc[nt][1], sacc[nt][2], sacc[nt][3],
                     qf[ks][0], qf[ks][1], qf[ks][2], qf[ks][3], b0, b1);
            }
        }

        // Online softmax (row = 4 lanes: xor 1,2)
        float cm0 = sacc[0][0], cm1 = sacc[0][2];
#pragma unroll
        for (int nt = 0; nt < 8; nt++) {
            cm0 = fmaxf(cm0, fmaxf(sacc[nt][0], sacc[nt][1]));
            cm1 = fmaxf(cm1, fmaxf(sacc[nt][2], sacc[nt][3]));
        }
        cm0 = fmaxf(cm0, __shfl_xor_sync(0xffffffffu, cm0, 1));
        cm0 = fmaxf(cm0, __shfl_xor_sync(0xffffffffu, cm0, 2));
        cm1 = fmaxf(cm1, __shfl_xor_sync(0xffffffffu, cm1, 1));
        cm1 = fmaxf(cm1, __shfl_xor_sync(0xffffffffu, cm1, 2));
        float nM0 = fmaxf(M0, cm0), nM1 = fmaxf(M1, cm1);
        float a0 = __expf(M0 - nM0), a1 = __expf(M1 - nM1);
        float rs0 = 0.f, rs1 = 0.f;
#pragma unroll
        for (int nt = 0; nt < 8; nt++) {
            sacc[nt][0] = __expf(sacc[nt][0] - nM0);
            sacc[nt][1] = __expf(sacc[nt][1] - nM0);
            sacc[nt][2] = __expf(sacc[nt][2] - nM1);
            sacc[nt][3] = __expf(sacc[nt][3] - nM1);
            rs0 += sacc[nt][0] + sacc[nt][1];
            rs1 += sacc[nt][2] + sacc[nt][3];
        }
        rs0 += __shfl_xor_sync(0xffffffffu, rs0, 1);
        rs0 += __shfl_xor_sync(0xffffffffu, rs0, 2);
        rs1 += __shfl_xor_sync(0xffffffffu, rs1, 1);
        rs1 += __shfl_xor_sync(0xffffffffu, rs1, 2);
        L0 = L0 * a0 + rs0;  M0 = nM0;
        L1 = L1 * a1 + rs1;  M1 = nM1;

        // Rescale O; park P in the warp-private smem slab (C-layout, fp32)
#pragma unroll
        for (int nt = 0; nt < 8; nt++) {
            oacc[nt][0] *= a0; oacc[nt][1] *= a0;
            oacc[nt][2] *= a1; oacc[nt][3] *= a1;
            *(float2*)&Pw[g * AS + nt * 8 + 2 * tq] =
                make_float2(sacc[nt][0], sacc[nt][1]);
            *(float2*)&Pw[(g + 8) * AS + nt * 8 + 2 * tq] =
                make_float2(sacc[nt][2], sacc[nt][3]);
        }
        __syncwarp();

        // Prefetch chunk kc+2 here: kreg/vreg not live across the QK peak.
        if (kc + 2 < NC) LDG_CHUNK(kc + 2);

        // O += P @ V
#pragma unroll
        for (int ks = 0; ks < 8; ks++) {
            int k0 = ks * 8;
            uint32_t pa0 = f2tf(Pw[g * AS + k0 + tq]);
            uint32_t pa1 = f2tf(Pw[(g + 8) * AS + k0 + tq]);
            uint32_t pa2 = f2tf(Pw[g * AS + k0 + tq + 4]);
            uint32_t pa3 = f2tf(Pw[(g + 8) * AS + k0 + tq + 4]);
#pragma unroll
            for (int nt = 0; nt < 8; nt++) {
                uint32_t b0 = Vb[(k0 + tq) * AS + nt * 8 + g];
                uint32_t b1 = Vb[(k0 + tq + 4) * AS + nt * 8 + g];
                mma8(oacc[nt][0], oacc[nt][1], oacc[nt][2], oacc[nt][3],
                     pa0, pa1, pa2, pa3, b0, b1);
            }
        }
        __syncthreads();   // all warps done reading buf p; next iter may STS it
    }
#undef LDG_CHUNK
#undef STS_CHUNK

    // Normalize, write out[b, n, h*64 + d]
    float i0 = 1.0f / L0, i1 = 1.0f / L1;
    int row0 = mb + warp * 16 + g;
#pragma unroll
    for (int nt = 0; nt < 8; nt++) {
        int col = h * DHEAD + nt * 8 + 2 * tq;
        *(float2*)(out + (seq0 + row0) * DMODEL + col) =
            make_float2(oacc[nt][0] * i0, oacc[nt][1] * i0);
        *(float2*)(out + (seq0 + row0 + 8) * DMODEL + col) =
            make_float2(oacc[nt][2] * i1, oacc[nt][3] * i1);
    }
}

// ---------------------------------------------------------------------------
extern "C" void kernel_launch(void* const* d_in, const int* in_sizes, int n_in,
                              void* d_out, int out_size)
{
    (void)in_sizes; (void)n_in; (void)out_size;
    const float* x      = (const float*)d_in[0];
    const float* w_qkv  = (const float*)d_in[1];
    const float* w_proj = (const float*)d_in[2];
    const float* b_proj = (const float*)d_in[3];
    const float* gamma  = (const float*)d_in[4];
    const float* beta   = (const float*)d_in[5];
    float* out = (float*)d_out;

    float *xn, *qkvp, *att;
    cudaGetSymbolAddress((void**)&xn,   g_xn);
    cudaGetSymbolAddress((void**)&qkvp, g_qkv);
    cudaGetSymbolAddress((void**)&att,  g_att);

    const int SMEM = ATTN_SMEM_FLOATS * (int)sizeof(float);
    cudaFuncSetAttribute(attn_tf32,
                         cudaFuncAttributeMaxDynamicSharedMemorySize, SMEM);

    ln_kernel<<<ROWS, 128>>>(x, gamma, beta, xn);
    mm_tf32<false><<<dim3(QKVDIM / 128, ROWS / 128), 256>>>(
        xn, w_qkv, nullptr, qkvp, QKVDIM);
    attn_tf32<<<dim3(SEQ / AROWS, BATCH * NHEAD), 512, SMEM>>>(qkvp, att);
    mm_tf32<true><<<dim3(DMODEL / 128, ROWS / 128), 256>>>(
        att, w_proj, b_proj, out, DMODEL);
}

// round 6
// speedup vs baseline: 1.8045x; 1.1749x over previous
#include <cuda_runtime.h>
#include <cstdint>

#define BATCH  8
#define SEQ    2048
#define DMODEL 512
#define NHEAD  8
#define DHEAD  64
#define ROWS   (BATCH * SEQ)     // 16384
#define QKVDIM (3 * DMODEL)      // 1536

// Scratch (allocation-free contract: __device__ globals)
__device__ float g_xn [ROWS * DMODEL];   // 32 MB
__device__ float g_qkv[ROWS * QKVDIM];   // 96 MB
__device__ float g_att[ROWS * DMODEL];   // 32 MB

// ---------------------------------------------------------------------------
// helpers: tf32 convert + m16n8k8 tf32 mma
// ---------------------------------------------------------------------------
__device__ __forceinline__ uint32_t f2tf(float x) {
    uint32_t r;
    asm("cvt.rna.tf32.f32 %0, %1;" : "=r"(r) : "f"(x));
    return r;
}

__device__ __forceinline__ void mma8(float& c0, float& c1, float& c2, float& c3,
                                     uint32_t a0, uint32_t a1, uint32_t a2, uint32_t a3,
                                     uint32_t b0, uint32_t b1) {
    asm volatile(
        "mma.sync.aligned.m16n8k8.row.col.f32.tf32.tf32.f32 "
        "{%0,%1,%2,%3}, {%4,%5,%6,%7}, {%8,%9}, {%0,%1,%2,%3};"
        : "+f"(c0), "+f"(c1), "+f"(c2), "+f"(c3)
        : "r"(a0), "r"(a1), "r"(a2), "r"(a3), "r"(b0), "r"(b1));
}

// ---------------------------------------------------------------------------
// LayerNorm: one block (128 threads) per row of 512
// ---------------------------------------------------------------------------
__global__ __launch_bounds__(128) void ln_kernel(
    const float* __restrict__ x, const float* __restrict__ gamma,
    const float* __restrict__ beta, float* __restrict__ out)
{
    int row = blockIdx.x;
    int t   = threadIdx.x;
    const float* xr = x + (size_t)row * DMODEL;
    float4 v = *(const float4*)(xr + t * 4);
    float s  = v.x + v.y + v.z + v.w;
    float ss = v.x * v.x + v.y * v.y + v.z * v.z + v.w * v.w;
#pragma unroll
    for (int m = 16; m; m >>= 1) {
        s  += __shfl_xor_sync(0xffffffffu, s,  m);
        ss += __shfl_xor_sync(0xffffffffu, ss, m);
    }
    __shared__ float red[8];
    if ((t & 31) == 0) { red[t >> 5] = s; red[4 + (t >> 5)] = ss; }
    __syncthreads();
    float tot  = red[0] + red[1] + red[2] + red[3];
    float tot2 = red[4] + red[5] + red[6] + red[7];
    float mu   = tot * (1.0f / DMODEL);
    float var  = tot2 * (1.0f / DMODEL) - mu * mu;
    float rstd = rsqrtf(var + 1e-6f);
    float4 g = *(const float4*)(gamma + t * 4);
    float4 b = *(const float4*)(beta  + t * 4);
    float4 o;
    o.x = (v.x - mu) * rstd * g.x + b.x;
    o.y = (v.y - mu) * rstd * g.y + b.y;
    o.z = (v.z - mu) * rstd * g.z + b.z;
    o.w = (v.w - mu) * rstd * g.w + b.w;
    *(float4*)(out + (size_t)row * DMODEL + t * 4) = o;
}

// ---------------------------------------------------------------------------
// tf32 tensor-core GEMM (NT): C[M,N] = A[M,K=512] * B[N,K=512]^T (+bias)
// Same layout/indexing as measured-best version, now DOUBLE-BUFFERED:
// one __syncthreads per k-tile.
// ---------------------------------------------------------------------------
#define GK 512
#define GS 20   // smem row stride (uint32)

template <bool BIAS>
__global__ __launch_bounds__(256, 2) void mm_tf32(
    const float* __restrict__ A, const float* __restrict__ Bw,
    const float* __restrict__ bias, float* __restrict__ C, int N)
{
    __shared__ uint32_t As[2][128][GS];
    __shared__ uint32_t Bs[2][128][GS];
    int t    = threadIdx.x;
    int m0   = blockIdx.y * 128, n0 = blockIdx.x * 128;
    int warp = t >> 5, lane = t & 31, g = lane >> 2, tq = lane & 3;
    int wm   = (warp >> 2) * 64, wn = (warp & 3) * 32;

    int lrow = t >> 2;        // 0..63 (and +64)
    int lk4  = t & 3;         // which float4 within the 16-k tile
    const float* Ag = A  + (size_t)(m0 + lrow) * GK + lk4 * 4;
    const float* Bg = Bw + (size_t)(n0 + lrow) * GK + lk4 * 4;

    float acc[4][4][4];
#pragma unroll
    for (int i = 0; i < 4; i++)
#pragma unroll
        for (int j = 0; j < 4; j++)
#pragma unroll
            for (int r = 0; r < 4; r++) acc[i][j][r] = 0.f;

    float4 ra0 = *(const float4*)Ag;
    float4 ra1 = *(const float4*)(Ag + (size_t)64 * GK);
    float4 rb0 = *(const float4*)Bg;
    float4 rb1 = *(const float4*)(Bg + (size_t)64 * GK);

#define GSTASH(buf)                                                          \
    do {                                                                     \
        *(uint4*)&As[buf][lrow][lk4 * 4] =                                   \
            make_uint4(f2tf(ra0.x), f2tf(ra0.y), f2tf(ra0.z), f2tf(ra0.w));  \
        *(uint4*)&As[buf][lrow + 64][lk4 * 4] =                              \
            make_uint4(f2tf(ra1.x), f2tf(ra1.y), f2tf(ra1.z), f2tf(ra1.w));  \
        *(uint4*)&Bs[buf][lrow][lk4 * 4] =                                   \
            make_uint4(f2tf(rb0.x), f2tf(rb0.y), f2tf(rb0.z), f2tf(rb0.w));  \
        *(uint4*)&Bs[buf][lrow + 64][lk4 * 4] =                              \
            make_uint4(f2tf(rb1.x), f2tf(rb1.y), f2tf(rb1.z), f2tf(rb1.w));  \
    } while (0)

    GSTASH(0);
    __syncthreads();

    const int NT = GK / 16;
    for (int kt = 0; kt < NT; kt++) {
        int buf = kt & 1;
        if (kt + 1 < NT) {
            ra0 = *(const float4*)(Ag + (kt + 1) * 16);
            ra1 = *(const float4*)(Ag + (size_t)64 * GK + (kt + 1) * 16);
            rb0 = *(const float4*)(Bg + (kt + 1) * 16);
            rb1 = *(const float4*)(Bg + (size_t)64 * GK + (kt + 1) * 16);
        }
#pragma unroll
        for (int ks = 0; ks < 2; ks++) {
            int k0 = ks * 8;
            uint32_t af[4][4], bf[4][2];
#pragma unroll
            for (int mt = 0; mt < 4; mt++) {
                int r = wm + mt * 16 + g;
                af[mt][0] = As[buf][r][k0 + tq];
                af[mt][1] = As[buf][r + 8][k0 + tq];
                af[mt][2] = As[buf][r][k0 + tq + 4];
                af[mt][3] = As[buf][r + 8][k0 + tq + 4];
            }
#pragma unroll
            for (int nt = 0; nt < 4; nt++) {
                int r = wn + nt * 8 + g;
                bf[nt][0] = Bs[buf][r][k0 + tq];
                bf[nt][1] = Bs[buf][r][k0 + tq + 4];
            }
#pragma unroll
            for (int mt = 0; mt < 4; mt++)
#pragma unroll
                for (int nt = 0; nt < 4; nt++)
                    mma8(acc[mt][nt][0], acc[mt][nt][1], acc[mt][nt][2], acc[mt][nt][3],
                         af[mt][0], af[mt][1], af[mt][2], af[mt][3],
                         bf[nt][0], bf[nt][1]);
        }
        if (kt + 1 < NT) GSTASH(buf ^ 1);
        __syncthreads();
    }
#undef GSTASH

#pragma unroll
    for (int mt = 0; mt < 4; mt++) {
#pragma unroll
        for (int nt = 0; nt < 4; nt++) {
            int row = m0 + wm + mt * 16 + g;
            int col = n0 + wn + nt * 8 + 2 * tq;
            float b0 = 0.f, b1 = 0.f;
            if (BIAS) { b0 = bias[col]; b1 = bias[col + 1]; }
            float2 v0 = make_float2(acc[mt][nt][0] + b0, acc[mt][nt][1] + b1);
            float2 v1 = make_float2(acc[mt][nt][2] + b0, acc[mt][nt][3] + b1);
            *(float2*)(C + (size_t)row * N + col)       = v0;
            *(float2*)(C + (size_t)(row + 8) * N + col) = v1;
        }
    }
}

// ---------------------------------------------------------------------------
// Flash attention, tf32 tensor cores.
// CTA = 256 Q rows of one (b,h); 256 threads = 8 warps; warp owns 32 rows
// (2 m16 tiles) so every K/V fragment LDS feeds 2 MMAs -> smem crossbar
// traffic per chunk drops ~1.7x vs 16-rows-per-warp.
// K/V double-buffered, pre-converted tf32 bits. P parked as tf32 bits.
// ---------------------------------------------------------------------------
#define AS 68   // attn smem stride (words)
#define AROWS 256
#define ATTN_SMEM_FLOATS (AROWS * AS + 4 * 64 * AS)   // 139264 bytes

__global__ __launch_bounds__(256, 1) void attn_tf32(
    const float* __restrict__ qkv, float* __restrict__ out)
{
    extern __shared__ float sm[];
    float*    QP = sm;                           // [256][AS] Q stage, P slabs
    uint32_t* Ks = (uint32_t*)(sm + AROWS * AS); // [2][64][AS] key-major tf32
    uint32_t* Vs = Ks + 2 * 64 * AS;             // [2][64][AS] key-major tf32

    int t = threadIdx.x, warp = t >> 5, lane = t & 31, g = lane >> 2, tq = lane & 3;
    int bh = blockIdx.y, b = bh >> 3, h = bh & 7;
    int mb = blockIdx.x * AROWS;
    size_t seq0 = (size_t)b * SEQ;
    const float* base  = qkv + seq0 * QKVDIM + h * DHEAD;
    const float* kbase = base + DMODEL;
    const float* vbase = base + 2 * DMODEL;

    int d4 = t & 15, r0 = t >> 4;   // r0: 0..15

    // Stage Q tile (coalesced)
    {
#pragma unroll
        for (int j = 0; j < 16; j++) {
            int row = r0 + 16 * j;
            *(float4*)&QP[row * AS + d4 * 4] =
                *(const float4*)(base + (size_t)(mb + row) * QKVDIM + d4 * 4);
        }
    }
    __syncthreads();

    // Per-warp Q fragments (scaled), 2 m-tiles
    uint32_t qf[2][8][4];
    float*    Pw  = QP + warp * 32 * AS;   // warp-private 32-row slab
    uint32_t* Pwu = (uint32_t*)Pw;
    {
        const float scale = 0.125f;    // 1/sqrt(64)
#pragma unroll
        for (int mt = 0; mt < 2; mt++)
#pragma unroll
            for (int ks = 0; ks < 8; ks++) {
                int rA = (mt * 16 + g) * AS, rB = (mt * 16 + g + 8) * AS;
                qf[mt][ks][0] = f2tf(Pw[rA + ks * 8 + tq] * scale);
                qf[mt][ks][1] = f2tf(Pw[rB + ks * 8 + tq] * scale);
                qf[mt][ks][2] = f2tf(Pw[rA + ks * 8 + tq + 4] * scale);
                qf[mt][ks][3] = f2tf(Pw[rB + ks * 8 + tq + 4] * scale);
            }
    }

    float oacc[2][8][4];
#pragma unroll
    for (int mt = 0; mt < 2; mt++)
#pragma unroll
        for (int nt = 0; nt < 8; nt++)
#pragma unroll
            for (int r = 0; r < 4; r++) oacc[mt][nt][r] = 0.f;
    float Mm[2][2], Ll[2][2];
#pragma unroll
    for (int mt = 0; mt < 2; mt++) {
        Mm[mt][0] = -1e30f; Mm[mt][1] = -1e30f;
        Ll[mt][0] = 0.f;    Ll[mt][1] = 0.f;
    }

    const int NC = SEQ / 64;
    float4 kreg[4], vreg[4];

#define LDG_CHUNK(c)                                                          \
    do {                                                                      \
        size_t key = (size_t)((c) * 64 + r0);                                 \
        _Pragma("unroll")                                                     \
        for (int j = 0; j < 4; j++) {                                         \
            kreg[j] = *(const float4*)(kbase + (key + 16 * j) * QKVDIM + d4 * 4); \
            vreg[j] = *(const float4*)(vbase + (key + 16 * j) * QKVDIM + d4 * 4); \
        }                                                                     \
    } while (0)

#define STS_CHUNK(p)                                                          \
    do {                                                                      \
        uint32_t* kb = Ks + (p) * 64 * AS;                                    \
        uint32_t* vb = Vs + (p) * 64 * AS;                                    \
        _Pragma("unroll")                                                     \
        for (int j = 0; j < 4; j++) {                                         \
            int row = r0 + 16 * j;                                            \
            *(uint4*)&kb[row * AS + d4 * 4] = make_uint4(                     \
                f2tf(kreg[j].x), f2tf(kreg[j].y), f2tf(kreg[j].z), f2tf(kreg[j].w)); \
            *(uint4*)&vb[row * AS + d4 * 4] = make_uint4(                     \
                f2tf(vreg[j].x), f2tf(vreg[j].y), f2tf(vreg[j].z), f2tf(vreg[j].w)); \
        }                                                                     \
    } while (0)

    LDG_CHUNK(0);
    STS_CHUNK(0);
    LDG_CHUNK(1);
    __syncthreads();

    for (int kc = 0; kc < NC; kc++) {
        int p = kc & 1;
        if (kc + 1 < NC) STS_CHUNK(p ^ 1);   // consumes kreg/vreg
        const uint32_t* Kb = Ks + p * 64 * AS;
        const uint32_t* Vb = Vs + p * 64 * AS;

        // S = (Q*scale) K^T : nt = key group, ks = d group; 2 m-tiles per frag
        float sacc[2][8][4];
#pragma unroll
        for (int mt = 0; mt < 2; mt++)
#pragma unroll
            for (int nt = 0; nt < 8; nt++)
#pragma unroll
                for (int r = 0; r < 4; r++) sacc[mt][nt][r] = 0.f;

#pragma unroll
        for (int ks = 0; ks < 8; ks++) {
            int k0 = ks * 8;
#pragma unroll
            for (int nt = 0; nt < 8; nt++) {
                int kr = nt * 8 + g;
                uint32_t b0 = Kb[kr * AS + k0 + tq];
                uint32_t b1 = Kb[kr * AS + k0 + tq + 4];
                mma8(sacc[0][nt][0], sacc[0][nt][1], sacc[0][nt][2], sacc[0][nt][3],
                     qf[0][ks][0], qf[0][ks][1], qf[0][ks][2], qf[0][ks][3], b0, b1);
                mma8(sacc[1][nt][0], sacc[1][nt][1], sacc[1][nt][2], sacc[1][nt][3],
                     qf[1][ks][0], qf[1][ks][1], qf[1][ks][2], qf[1][ks][3], b0, b1);
            }
        }

        // Online softmax per m-tile (row = 4 lanes: xor 1,2)
#pragma unroll
        for (int mt = 0; mt < 2; mt++) {
            float cm0 = sacc[mt][0][0], cm1 = sacc[mt][0][2];
#pragma unroll
            for (int nt = 0; nt < 8; nt++) {
                cm0 = fmaxf(cm0, fmaxf(sacc[mt][nt][0], sacc[mt][nt][1]));
                cm1 = fmaxf(cm1, fmaxf(sacc[mt][nt][2], sacc[mt][nt][3]));
            }
            cm0 = fmaxf(cm0, __shfl_xor_sync(0xffffffffu, cm0, 1));
            cm0 = fmaxf(cm0, __shfl_xor_sync(0xffffffffu, cm0, 2));
            cm1 = fmaxf(cm1, __shfl_xor_sync(0xffffffffu, cm1, 1));
            cm1 = fmaxf(cm1, __shfl_xor_sync(0xffffffffu, cm1, 2));
            float nM0 = fmaxf(Mm[mt][0], cm0), nM1 = fmaxf(Mm[mt][1], cm1);
            float a0 = __expf(Mm[mt][0] - nM0), a1 = __expf(Mm[mt][1] - nM1);
            float rs0 = 0.f, rs1 = 0.f;
#pragma unroll
            for (int nt = 0; nt < 8; nt++) {
                sacc[mt][nt][0] = __expf(sacc[mt][nt][0] - nM0);
                sacc[mt][nt][1] = __expf(sacc[mt][nt][1] - nM0);
                sacc[mt][nt][2] = __expf(sacc[mt][nt][2] - nM1);
                sacc[mt][nt][3] = __expf(sacc[mt][nt][3] - nM1);
                rs0 += sacc[mt][nt][0] + sacc[mt][nt][1];
                rs1 += sacc[mt][nt][2] + sacc[mt][nt][3];
            }
            rs0 += __shfl_xor_sync(0xffffffffu, rs0, 1);
            rs0 += __shfl_xor_sync(0xffffffffu, rs0, 2);
            rs1 += __shfl_xor_sync(0xffffffffu, rs1, 1);
            rs1 += __shfl_xor_sync(0xffffffffu, rs1, 2);
            Ll[mt][0] = Ll[mt][0] * a0 + rs0;  Mm[mt][0] = nM0;
            Ll[mt][1] = Ll[mt][1] * a1 + rs1;  Mm[mt][1] = nM1;

            // Rescale O; park P as tf32 bits in the warp slab
#pragma unroll
            for (int nt = 0; nt < 8; nt++) {
                oacc[mt][nt][0] *= a0; oacc[mt][nt][1] *= a0;
                oacc[mt][nt][2] *= a1; oacc[mt][nt][3] *= a1;
                *(uint2*)&Pwu[(mt * 16 + g) * AS + nt * 8 + 2 * tq] =
                    make_uint2(f2tf(sacc[mt][nt][0]), f2tf(sacc[mt][nt][1]));
                *(uint2*)&Pwu[(mt * 16 + g + 8) * AS + nt * 8 + 2 * tq] =
                    make_uint2(f2tf(sacc[mt][nt][2]), f2tf(sacc[mt][nt][3]));
            }
        }
        __syncwarp();

        // Prefetch chunk kc+2 (kreg/vreg not live across QK reg peak)
        if (kc + 2 < NC) LDG_CHUNK(kc + 2);

        // O += P @ V
#pragma unroll
        for (int ks = 0; ks < 8; ks++) {
            int k0 = ks * 8;
            uint32_t pa[2][4];
#pragma unroll
            for (int mt = 0; mt < 2; mt++) {
                pa[mt][0] = Pwu[(mt * 16 + g) * AS + k0 + tq];
                pa[mt][1] = Pwu[(mt * 16 + g + 8) * AS + k0 + tq];
                pa[mt][2] = Pwu[(mt * 16 + g) * AS + k0 + tq + 4];
                pa[mt][3] = Pwu[(mt * 16 + g + 8) * AS + k0 + tq + 4];
            }
#pragma unroll
            for (int nt = 0; nt < 8; nt++) {
                uint32_t b0 = Vb[(k0 + tq) * AS + nt * 8 + g];
                uint32_t b1 = Vb[(k0 + tq + 4) * AS + nt * 8 + g];
                mma8(oacc[0][nt][0], oacc[0][nt][1], oacc[0][nt][2], oacc[0][nt][3],
                     pa[0][0], pa[0][1], pa[0][2], pa[0][3], b0, b1);
                mma8(oacc[1][nt][0], oacc[1][nt][1], oacc[1][nt][2], oacc[1][nt][3],
                     pa[1][0], pa[1][1], pa[1][2], pa[1][3], b0, b1);
            }
        }
        __syncthreads();   // all warps done reading buf p; next iter may STS it
    }
#undef LDG_CHUNK
#undef STS_CHUNK

    // Normalize, write out[b, n, h*64 + d]
#pragma unroll
    for (int mt = 0; mt < 2; mt++) {
        float i0 = 1.0f / Ll[mt][0], i1 = 1.0f / Ll[mt][1];
        int row0 = mb + warp * 32 + mt * 16 + g;
#pragma unroll
        for (int nt = 0; nt < 8; nt++) {
            int col = h * DHEAD + nt * 8 + 2 * tq;
            *(float2*)(out + (seq0 + row0) * DMODEL + col) =
                make_float2(oacc[mt][nt][0] * i0, oacc[mt][nt][1] * i0);
            *(float2*)(out + (seq0 + row0 + 8) * DMODEL + col) =
                make_float2(oacc[mt][nt][2] * i1, oacc[mt][nt][3] * i1);
        }
    }
}

// ---------------------------------------------------------------------------
extern "C" void kernel_launch(void* const* d_in, const int* in_sizes, int n_in,
                              void* d_out, int out_size)
{
    (void)in_sizes; (void)n_in; (void)out_size;
    const float* x      = (const float*)d_in[0];
    const float* w_qkv  = (const float*)d_in[1];
    const float* w_proj = (const float*)d_in[2];
    const float* b_proj = (const float*)d_in[3];
    const float* gamma  = (const float*)d_in[4];
    const float* beta   = (const float*)d_in[5];
    float* out = (float*)d_out;

    float *xn, *qkvp, *att;
    cudaGetSymbolAddress((void**)&xn,   g_xn);
    cudaGetSymbolAddress((void**)&qkvp, g_qkv);
    cudaGetSymbolAddress((void**)&att,  g_att);

    const int SMEM = ATTN_SMEM_FLOATS * (int)sizeof(float);
    cudaFuncSetAttribute(attn_tf32,
                         cudaFuncAttributeMaxDynamicSharedMemorySize, SMEM);

    ln_kernel<<<ROWS, 128>>>(x, gamma, beta, xn);
    mm_tf32<false><<<dim3(QKVDIM / 128, ROWS / 128), 256>>>(
        xn, w_qkv, nullptr, qkvp, QKVDIM);
    attn_tf32<<<dim3(SEQ / AROWS, BATCH * NHEAD), 256, SMEM>>>(qkvp, att);
    mm_tf32<true><<<dim3(DMODEL / 128, ROWS / 128), 256>>>(
        att, w_proj, b_proj, out, DMODEL);
}

// round 7
// speedup vs baseline: 2.6580x; 1.4730x over previous
#include <cuda_runtime.h>
#include <cstdint>

#define BATCH  8
#define SEQ    2048
#define DMODEL 512
#define NHEAD  8
#define DHEAD  64
#define ROWS   (BATCH * SEQ)     // 16384
#define QKVDIM (3 * DMODEL)      // 1536

__device__ float g_xn [ROWS * DMODEL];
__device__ float g_qkv[ROWS * QKVDIM];
__device__ float g_att[ROWS * DMODEL];

// ---------------------------------------------------------------------------
// helpers: pack 2 floats -> half2 (lo in lower 16), m16n8k16 fp16 mma
// ---------------------------------------------------------------------------
__device__ __forceinline__ uint32_t f2h2(float lo, float hi) {
    uint32_t r;
    asm("cvt.rn.f16x2.f32 %0, %1, %2;" : "=r"(r) : "f"(hi), "f"(lo));
    return r;
}

__device__ __forceinline__ void mma16(float& c0, float& c1, float& c2, float& c3,
                                      uint32_t a0, uint32_t a1, uint32_t a2, uint32_t a3,
                                      uint32_t b0, uint32_t b1) {
    asm volatile(
        "mma.sync.aligned.m16n8k16.row.col.f32.f16.f16.f32 "
        "{%0,%1,%2,%3}, {%4,%5,%6,%7}, {%8,%9}, {%0,%1,%2,%3};"
        : "+f"(c0), "+f"(c1), "+f"(c2), "+f"(c3)
        : "r"(a0), "r"(a1), "r"(a2), "r"(a3), "r"(b0), "r"(b1));
}

// ---------------------------------------------------------------------------
// LayerNorm (unchanged)
// ---------------------------------------------------------------------------
__global__ __launch_bounds__(128) void ln_kernel(
    const float* __restrict__ x, const float* __restrict__ gamma,
    const float* __restrict__ beta, float* __restrict__ out)
{
    int row = blockIdx.x;
    int t   = threadIdx.x;
    const float* xr = x + (size_t)row * DMODEL;
    float4 v = *(const float4*)(xr + t * 4);
    float s  = v.x + v.y + v.z + v.w;
    float ss = v.x * v.x + v.y * v.y + v.z * v.z + v.w * v.w;
#pragma unroll
    for (int m = 16; m; m >>= 1) {
        s  += __shfl_xor_sync(0xffffffffu, s,  m);
        ss += __shfl_xor_sync(0xffffffffu, ss, m);
    }
    __shared__ float red[8];
    if ((t & 31) == 0) { red[t >> 5] = s; red[4 + (t >> 5)] = ss; }
    __syncthreads();
    float tot  = red[0] + red[1] + red[2] + red[3];
    float tot2 = red[4] + red[5] + red[6] + red[7];
    float mu   = tot * (1.0f / DMODEL);
    float var  = tot2 * (1.0f / DMODEL) - mu * mu;
    float rstd = rsqrtf(var + 1e-6f);
    float4 g = *(const float4*)(gamma + t * 4);
    float4 b = *(const float4*)(beta  + t * 4);
    float4 o;
    o.x = (v.x - mu) * rstd * g.x + b.x;
    o.y = (v.y - mu) * rstd * g.y + b.y;
    o.z = (v.z - mu) * rstd * g.z + b.z;
    o.w = (v.w - mu) * rstd * g.w + b.w;
    *(float4*)(out + (size_t)row * DMODEL + t * 4) = o;
}

// ---------------------------------------------------------------------------
// fp16 tensor-core GEMM (NT): C[M,N] = A[M,K=512] * B[N,K]^T (+bias)
// CTA 128x128x32 tiles, double-buffered half2 smem (16 words/row + pad).
// 8 warps (2m x 4n), warp tile 64x32; m16n8k16, 2 k-steps per tile.
// ---------------------------------------------------------------------------
#define GK 512
#define GS 20   // smem row stride in half2 words (16 data + 4 pad)

template <bool BIAS>
__global__ __launch_bounds__(256, 2) void mm_h(
    const float* __restrict__ A, const float* __restrict__ Bw,
    const float* __restrict__ bias, float* __restrict__ C, int N)
{
    __shared__ uint32_t As[2][128][GS];
    __shared__ uint32_t Bs[2][128][GS];
    int t    = threadIdx.x;
    int m0   = blockIdx.y * 128, n0 = blockIdx.x * 128;
    int warp = t >> 5, lane = t & 31, g = lane >> 2, tq = lane & 3;
    int wm   = (warp >> 2) * 64, wn = (warp & 3) * 32;

    int lrow = t >> 2;        // 0..63 (and +64)
    int lk2  = t & 3;         // 8-float group within the 32-k tile
    const float* Ag = A  + (size_t)(m0 + lrow) * GK + lk2 * 8;
    const float* Bg = Bw + (size_t)(n0 + lrow) * GK + lk2 * 8;

    float acc[4][4][4];
#pragma unroll
    for (int i = 0; i < 4; i++)
#pragma unroll
        for (int j = 0; j < 4; j++)
#pragma unroll
            for (int r = 0; r < 4; r++) acc[i][j][r] = 0.f;

    uint4 pA0, pA1, pB0, pB1;
#define GLOAD(kt)                                                             \
    do {                                                                      \
        float4 a = *(const float4*)(Ag + (kt) * 32);                          \
        float4 b = *(const float4*)(Ag + (kt) * 32 + 4);                      \
        pA0 = make_uint4(f2h2(a.x, a.y), f2h2(a.z, a.w),                      \
                         f2h2(b.x, b.y), f2h2(b.z, b.w));                     \
        a = *(const float4*)(Ag + (size_t)64 * GK + (kt) * 32);               \
        b = *(const float4*)(Ag + (size_t)64 * GK + (kt) * 32 + 4);           \
        pA1 = make_uint4(f2h2(a.x, a.y), f2h2(a.z, a.w),                      \
                         f2h2(b.x, b.y), f2h2(b.z, b.w));                     \
        a = *(const float4*)(Bg + (kt) * 32);                                 \
        b = *(const float4*)(Bg + (kt) * 32 + 4);                             \
        pB0 = make_uint4(f2h2(a.x, a.y), f2h2(a.z, a.w),                      \
                         f2h2(b.x, b.y), f2h2(b.z, b.w));                     \
        a = *(const float4*)(Bg + (size_t)64 * GK + (kt) * 32);               \
        b = *(const float4*)(Bg + (size_t)64 * GK + (kt) * 32 + 4);           \
        pB1 = make_uint4(f2h2(a.x, a.y), f2h2(a.z, a.w),                      \
                         f2h2(b.x, b.y), f2h2(b.z, b.w));                     \
    } while (0)

#define GSTASH(buf)                                                           \
    do {                                                                      \
        *(uint4*)&As[buf][lrow][lk2 * 4]      = pA0;                          \
        *(uint4*)&As[buf][lrow + 64][lk2 * 4] = pA1;                          \
        *(uint4*)&Bs[buf][lrow][lk2 * 4]      = pB0;                          \
        *(uint4*)&Bs[buf][lrow + 64][lk2 * 4] = pB1;                          \
    } while (0)

    GLOAD(0);
    GSTASH(0);
    __syncthreads();

    const int NT = GK / 32;   // 16
    for (int kt = 0; kt < NT; kt++) {
        int buf = kt & 1;
        if (kt + 1 < NT) GLOAD(kt + 1);
#pragma unroll
        for (int ks = 0; ks < 2; ks++) {
            int k0 = ks * 8;
            uint32_t af[4][4], bf[4][2];
#pragma unroll
            for (int mt = 0; mt < 4; mt++) {
                int r = wm + mt * 16 + g;
                af[mt][0] = As[buf][r][k0 + tq];
                af[mt][1] = As[buf][r + 8][k0 + tq];
                af[mt][2] = As[buf][r][k0 + tq + 4];
                af[mt][3] = As[buf][r + 8][k0 + tq + 4];
            }
#pragma unroll
            for (int nt = 0; nt < 4; nt++) {
                int r = wn + nt * 8 + g;
                bf[nt][0] = Bs[buf][r][k0 + tq];
                bf[nt][1] = Bs[buf][r][k0 + tq + 4];
            }
#pragma unroll
            for (int mt = 0; mt < 4; mt++)
#pragma unroll
                for (int nt = 0; nt < 4; nt++)
                    mma16(acc[mt][nt][0], acc[mt][nt][1], acc[mt][nt][2], acc[mt][nt][3],
                          af[mt][0], af[mt][1], af[mt][2], af[mt][3],
                          bf[nt][0], bf[nt][1]);
        }
        if (kt + 1 < NT) GSTASH(buf ^ 1);
        __syncthreads();
    }
#undef GLOAD
#undef GSTASH

#pragma unroll
    for (int mt = 0; mt < 4; mt++) {
#pragma unroll
        for (int nt = 0; nt < 4; nt++) {
            int row = m0 + wm + mt * 16 + g;
            int col = n0 + wn + nt * 8 + 2 * tq;
            float b0 = 0.f, b1 = 0.f;
            if (BIAS) { b0 = bias[col]; b1 = bias[col + 1]; }
            float2 v0 = make_float2(acc[mt][nt][0] + b0, acc[mt][nt][1] + b1);
            float2 v1 = make_float2(acc[mt][nt][2] + b0, acc[mt][nt][3] + b1);
            *(float2*)(C + (size_t)row * N + col)       = v0;
            *(float2*)(C + (size_t)(row + 8) * N + col) = v1;
        }
    }
}

// ---------------------------------------------------------------------------
// Flash attention, fp16 tensor cores (fp32 softmax + accumulators).
// CTA = 256 Q rows; 256 threads = 8 warps x 32 rows (2 m16 tiles).
// Keys within a 64-chunk are LOGICALLY reordered: logical 2j,2j+1 = actual
// j, j+32 (softmax-invariant; K rows, P cols, V k-dim all use it) so V^T
// half2 key-pairs are packable by a single loader thread.
// K: [logical key][d half2] (36-word stride). V^T: [d][keypair ^ swizzle].
// Q/P slab: [row][k half2] (36-word stride).
// ---------------------------------------------------------------------------
#define QS2 36
#define AROWS 256
#define ATTN_SMEM_WORDS (AROWS * QS2 + 2 * 64 * QS2 + 2 * 64 * QS2)  // 18432

__global__ __launch_bounds__(256, 1) void attn_h(
    const float* __restrict__ qkv, float* __restrict__ out)
{
    extern __shared__ uint32_t smu[];
    uint32_t* QPu = smu;                      // [256][36] half2 (Q, then P)
    uint32_t* Ks  = smu + AROWS * QS2;        // [2][64][36] logical-key-major
    uint32_t* Vs  = Ks + 2 * 64 * QS2;        // [2][64][36] d-major V^T

    int t = threadIdx.x, warp = t >> 5, lane = t & 31, g = lane >> 2, tq = lane & 3;
    int bh = blockIdx.y, b = bh >> 3, h = bh & 7;
    int mb = blockIdx.x * AROWS;
    size_t seq0 = (size_t)b * SEQ;
    const float* base  = qkv + seq0 * QKVDIM + h * DHEAD;
    const float* kbase = base + DMODEL;
    const float* vbase = base + 2 * DMODEL;

    int d4 = t & 15, r0 = t >> 4;   // r0: 0..15

    // Stage Q (scaled, half2)
    {
        const float sc = 0.125f;
#pragma unroll
        for (int j = 0; j < 16; j++) {
            int row = r0 + 16 * j;
            float4 q = *(const float4*)(base + (size_t)(mb + row) * QKVDIM + d4 * 4);
            *(uint2*)&QPu[row * QS2 + d4 * 2] =
                make_uint2(f2h2(q.x * sc, q.y * sc), f2h2(q.z * sc, q.w * sc));
        }
    }
    __syncthreads();

    uint32_t* Pwu = QPu + warp * 32 * QS2;    // warp-private 32-row slab
    uint32_t qf[2][4][4];
#pragma unroll
    for (int mt = 0; mt < 2; mt++)
#pragma unroll
        for (int ks = 0; ks < 4; ks++) {
            int rA = (mt * 16 + g) * QS2, rB = (mt * 16 + g + 8) * QS2;
            qf[mt][ks][0] = Pwu[rA + ks * 8 + tq];
            qf[mt][ks][1] = Pwu[rB + ks * 8 + tq];
            qf[mt][ks][2] = Pwu[rA + ks * 8 + tq + 4];
            qf[mt][ks][3] = Pwu[rB + ks * 8 + tq + 4];
        }

    float oacc[2][8][4];
#pragma unroll
    for (int mt = 0; mt < 2; mt++)
#pragma unroll
        for (int nt = 0; nt < 8; nt++)
#pragma unroll
            for (int r = 0; r < 4; r++) oacc[mt][nt][r] = 0.f;
    float Mm[2][2], Ll[2][2];
#pragma unroll
    for (int mt = 0; mt < 2; mt++) {
        Mm[mt][0] = -1e30f; Mm[mt][1] = -1e30f;
        Ll[mt][0] = 0.f;    Ll[mt][1] = 0.f;
    }

    const int NC = SEQ / 64;
    uint2 kh[4];        // K rows r0+16i, packed half2
    uint32_t vh[8];     // V^T words: cols r0 (4 d-words), r0+16 (4 d-words)

#define LDG_CHUNK(c)                                                          \
    do {                                                                      \
        size_t key = (size_t)((c) * 64 + r0);                                 \
        float4 k0v, k1v, k2v, k3v, v0v, v1v, v2v, v3v;                        \
        k0v = *(const float4*)(kbase + (key +  0) * QKVDIM + d4 * 4);         \
        k1v = *(const float4*)(kbase + (key + 16) * QKVDIM + d4 * 4);         \
        k2v = *(const float4*)(kbase + (key + 32) * QKVDIM + d4 * 4);         \
        k3v = *(const float4*)(kbase + (key + 48) * QKVDIM + d4 * 4);         \
        v0v = *(const float4*)(vbase + (key +  0) * QKVDIM + d4 * 4);         \
        v1v = *(const float4*)(vbase + (key + 16) * QKVDIM + d4 * 4);         \
        v2v = *(const float4*)(vbase + (key + 32) * QKVDIM + d4 * 4);         \
        v3v = *(const float4*)(vbase + (key + 48) * QKVDIM + d4 * 4);         \
        kh[0] = make_uint2(f2h2(k0v.x, k0v.y), f2h2(k0v.z, k0v.w));           \
        kh[1] = make_uint2(f2h2(k1v.x, k1v.y), f2h2(k1v.z, k1v.w));           \
        kh[2] = make_uint2(f2h2(k2v.x, k2v.y), f2h2(k2v.z, k2v.w));           \
        kh[3] = make_uint2(f2h2(k3v.x, k3v.y), f2h2(k3v.z, k3v.w));           \
        const float* p0 = (const float*)&v0v; const float* p1 = (const float*)&v1v; \
        const float* p2 = (const float*)&v2v; const float* p3 = (const float*)&v3v; \
        _Pragma("unroll")                                                     \
        for (int k = 0; k < 4; k++) {                                         \
            vh[k]     = f2h2(p0[k], p2[k]);   /* keys r0, r0+32   */          \
            vh[4 + k] = f2h2(p1[k], p3[k]);   /* keys r0+16, +48  */          \
        }                                                                     \
    } while (0)

#define STS_CHUNK(p)                                                          \
    do {                                                                      \
        uint32_t* kb = Ks + (p) * 64 * QS2;                                   \
        uint32_t* vb = Vs + (p) * 64 * QS2;                                   \
        _Pragma("unroll")                                                     \
        for (int i = 0; i < 4; i++) {                                         \
            int r = r0 + 16 * i;                                              \
            int lam = ((r & 31) << 1) | (r >> 5);                             \
            *(uint2*)&kb[lam * QS2 + d4 * 2] = kh[i];                         \
        }                                                                     \
        _Pragma("unroll")                                                     \
        for (int k = 0; k < 4; k++) {                                         \
            int d = d4 * 4 + k;                                               \
            int sw = ((d >> 3) & 3) << 3;                                     \
            vb[d * QS2 + (r0 ^ sw)]        = vh[k];                           \
            vb[d * QS2 + ((r0 + 16) ^ sw)] = vh[4 + k];                       \
        }                                                                     \
    } while (0)

    LDG_CHUNK(0);
    STS_CHUNK(0);
    LDG_CHUNK(1);
    __syncthreads();

    for (int kc = 0; kc < NC; kc++) {
        int p = kc & 1;
        if (kc + 1 < NC) STS_CHUNK(p ^ 1);
        const uint32_t* Kb = Ks + p * 64 * QS2;
        const uint32_t* Vb = Vs + p * 64 * QS2;

        // S = Q K^T over logical keys
        float sacc[2][8][4];
#pragma unroll
        for (int mt = 0; mt < 2; mt++)
#pragma unroll
            for (int nt = 0; nt < 8; nt++)
#pragma unroll
                for (int r = 0; r < 4; r++) sacc[mt][nt][r] = 0.f;

#pragma unroll
        for (int ks = 0; ks < 4; ks++) {
            int k0 = ks * 8;
#pragma unroll
            for (int nt = 0; nt < 8; nt++) {
                int kr = (nt * 8 + g) * QS2;
                uint32_t b0 = Kb[kr + k0 + tq];
                uint32_t b1 = Kb[kr + k0 + tq + 4];
                mma16(sacc[0][nt][0], sacc[0][nt][1], sacc[0][nt][2], sacc[0][nt][3],
                      qf[0][ks][0], qf[0][ks][1], qf[0][ks][2], qf[0][ks][3], b0, b1);
                mma16(sacc[1][nt][0], sacc[1][nt][1], sacc[1][nt][2], sacc[1][nt][3],
                      qf[1][ks][0], qf[1][ks][1], qf[1][ks][2], qf[1][ks][3], b0, b1);
            }
        }

        // Online softmax per m-tile (fp32)
#pragma unroll
        for (int mt = 0; mt < 2; mt++) {
            float cm0 = sacc[mt][0][0], cm1 = sacc[mt][0][2];
#pragma unroll
            for (int nt = 0; nt < 8; nt++) {
                cm0 = fmaxf(cm0, fmaxf(sacc[mt][nt][0], sacc[mt][nt][1]));
                cm1 = fmaxf(cm1, fmaxf(sacc[mt][nt][2], sacc[mt][nt][3]));
            }
            cm0 = fmaxf(cm0, __shfl_xor_sync(0xffffffffu, cm0, 1));
            cm0 = fmaxf(cm0, __shfl_xor_sync(0xffffffffu, cm0, 2));
            cm1 = fmaxf(cm1, __shfl_xor_sync(0xffffffffu, cm1, 1));
            cm1 = fmaxf(cm1, __shfl_xor_sync(0xffffffffu, cm1, 2));
            float nM0 = fmaxf(Mm[mt][0], cm0), nM1 = fmaxf(Mm[mt][1], cm1);
            float a0 = __expf(Mm[mt][0] - nM0), a1 = __expf(Mm[mt][1] - nM1);
            float rs0 = 0.f, rs1 = 0.f;
#pragma unroll
            for (int nt = 0; nt < 8; nt++) {
                sacc[mt][nt][0] = __expf(sacc[mt][nt][0] - nM0);
                sacc[mt][nt][1] = __expf(sacc[mt][nt][1] - nM0);
                sacc[mt][nt][2] = __expf(sacc[mt][nt][2] - nM1);
                sacc[mt][nt][3] = __expf(sacc[mt][nt][3] - nM1);
                rs0 += sacc[mt][nt][0] + sacc[mt][nt][1];
                rs1 += sacc[mt][nt][2] + sacc[mt][nt][3];
            }
            rs0 += __shfl_xor_sync(0xffffffffu, rs0, 1);
            rs0 += __shfl_xor_sync(0xffffffffu, rs0, 2);
            rs1 += __shfl_xor_sync(0xffffffffu, rs1, 1);
            rs1 += __shfl_xor_sync(0xffffffffu, rs1, 2);
            Ll[mt][0] = Ll[mt][0] * a0 + rs0;  Mm[mt][0] = nM0;
            Ll[mt][1] = Ll[mt][1] * a1 + rs1;  Mm[mt][1] = nM1;

            // Rescale O; park P as half2 (cols = logical key pairs)
#pragma unroll
            for (int nt = 0; nt < 8; nt++) {
                oacc[mt][nt][0] *= a0; oacc[mt][nt][1] *= a0;
                oacc[mt][nt][2] *= a1; oacc[mt][nt][3] *= a1;
                Pwu[(mt * 16 + g) * QS2 + nt * 4 + tq] =
                    f2h2(sacc[mt][nt][0], sacc[mt][nt][1]);
                Pwu[(mt * 16 + g + 8) * QS2 + nt * 4 + tq] =
                    f2h2(sacc[mt][nt][2], sacc[mt][nt][3]);
            }
        }
        __syncwarp();

        if (kc + 2 < NC) LDG_CHUNK(kc + 2);

        // O += P @ V (k = logical keys; V^T swizzled reads)
#pragma unroll
        for (int ks = 0; ks < 4; ks++) {
            int k0 = ks * 8;
            uint32_t pa[2][4];
#pragma unroll
            for (int mt = 0; mt < 2; mt++) {
                pa[mt][0] = Pwu[(mt * 16 + g) * QS2 + k0 + tq];
                pa[mt][1] = Pwu[(mt * 16 + g + 8) * QS2 + k0 + tq];
                pa[mt][2] = Pwu[(mt * 16 + g) * QS2 + k0 + tq + 4];
                pa[mt][3] = Pwu[(mt * 16 + g + 8) * QS2 + k0 + tq + 4];
            }
#pragma unroll
            for (int nt = 0; nt < 8; nt++) {
                int sw = (nt & 3) << 3;
                int vr = (nt * 8 + g) * QS2;
                uint32_t b0 = Vb[vr + ((k0 + tq) ^ sw)];
                uint32_t b1 = Vb[vr + ((k0 + tq + 4) ^ sw)];
                mma16(oacc[0][nt][0], oacc[0][nt][1], oacc[0][nt][2], oacc[0][nt][3],
                      pa[0][0], pa[0][1], pa[0][2], pa[0][3], b0, b1);
                mma16(oacc[1][nt][0], oacc[1][nt][1], oacc[1][nt][2], oacc[1][nt][3],
                      pa[1][0], pa[1][1], pa[1][2], pa[1][3], b0, b1);
            }
        }
        __syncthreads();
    }
#undef LDG_CHUNK
#undef STS_CHUNK

    // Normalize + write out[b, n, h*64 + d]
#pragma unroll
    for (int mt = 0; mt < 2; mt++) {
        float i0 = 1.0f / Ll[mt][0], i1 = 1.0f / Ll[mt][1];
        int row0 = mb + warp * 32 + mt * 16 + g;
#pragma unroll
        for (int nt = 0; nt < 8; nt++) {
            int col = h * DHEAD + nt * 8 + 2 * tq;
            *(float2*)(out + (seq0 + row0) * DMODEL + col) =
                make_float2(oacc[mt][nt][0] * i0, oacc[mt][nt][1] * i0);
            *(float2*)(out + (seq0 + row0 + 8) * DMODEL + col) =
                make_float2(oacc[mt][nt][2] * i1, oacc[mt][nt][3] * i1);
        }
    }
}

// ---------------------------------------------------------------------------
extern "C" void kernel_launch(void* const* d_in, const int* in_sizes, int n_in,
                              void* d_out, int out_size)
{
    (void)in_sizes; (void)n_in; (void)out_size;
    const float* x      = (const float*)d_in[0];
    const float* w_qkv  = (const float*)d_in[1];
    const float* w_proj = (const float*)d_in[2];
    const float* b_proj = (const float*)d_in[3];
    const float* gamma  = (const float*)d_in[4];
    const float* beta   = (const float*)d_in[5];
    float* out = (float*)d_out;

    float *xn, *qkvp, *att;
    cudaGetSymbolAddress((void**)&xn,   g_xn);
    cudaGetSymbolAddress((void**)&qkvp, g_qkv);
    cudaGetSymbolAddress((void**)&att,  g_att);

    const int SMEM = ATTN_SMEM_WORDS * 4;
    cudaFuncSetAttribute(attn_h,
                         cudaFuncAttributeMaxDynamicSharedMemorySize, SMEM);

    ln_kernel<<<ROWS, 128>>>(x, gamma, beta, xn);
    mm_h<false><<<dim3(QKVDIM / 128, ROWS / 128), 256>>>(
        xn, w_qkv, nullptr, qkvp, QKVDIM);
    attn_h<<<dim3(SEQ / AROWS, BATCH * NHEAD), 256, SMEM>>>(qkvp, att);
    mm_h<true><<<dim3(DMODEL / 128, ROWS / 128), 256>>>(
        att, w_proj, b_proj, out, DMODEL);
}

// round 10
// speedup vs baseline: 3.2327x; 1.2162x over previous
#include <cuda_runtime.h>
#include <cuda_fp16.h>
#include <cstdint>

#define BATCH  8
#define SEQ    2048
#define DMODEL 512
#define NHEAD  8
#define DHEAD  64
#define ROWS   (BATCH * SEQ)     // 16384
#define QKVDIM (3 * DMODEL)      // 1536
#define GK     512

// Scratch (allocation-free contract)
__device__ uint32_t g_xnh  [ROWS * DMODEL / 2];   // LN out, fp16 pairs
__device__ uint32_t g_qkvh [ROWS * QKVDIM / 2];   // QKV out, fp16 pairs
__device__ uint32_t g_atth [ROWS * DMODEL / 2];   // attn out, fp16 pairs
__device__ uint32_t g_wqkvh[QKVDIM * DMODEL / 2]; // fp16 weights
__device__ uint32_t g_wprojh[DMODEL * DMODEL / 2];

// ---------------------------------------------------------------------------
// helpers
// ---------------------------------------------------------------------------
__device__ __forceinline__ uint32_t f2h2(float lo, float hi) {
    uint32_t r;
    asm("cvt.rn.f16x2.f32 %0, %1, %2;" : "=r"(r) : "f"(hi), "f"(lo));
    return r;
}

__device__ __forceinline__ uint32_t prmt(uint32_t a, uint32_t b, uint32_t sel) {
    uint32_t d;
    asm("prmt.b32 %0, %1, %2, %3;" : "=r"(d) : "r"(a), "r"(b), "r"(sel));
    return d;
}

__device__ __forceinline__ uint32_t ex2h2(uint32_t x) {
    uint32_t r;
    asm("ex2.approx.f16x2 %0, %1;" : "=r"(r) : "r"(x));
    return r;
}

__device__ __forceinline__ void mma16(float& c0, float& c1, float& c2, float& c3,
                                      uint32_t a0, uint32_t a1, uint32_t a2, uint32_t a3,
                                      uint32_t b0, uint32_t b1) {
    asm volatile(
        "mma.sync.aligned.m16n8k16.row.col.f32.f16.f16.f32 "
        "{%0,%1,%2,%3}, {%4,%5,%6,%7}, {%8,%9}, {%0,%1,%2,%3};"
        : "+f"(c0), "+f"(c1), "+f"(c2), "+f"(c3)
        : "r"(a0), "r"(a1), "r"(a2), "r"(a3), "r"(b0), "r"(b1));
}

// ---------------------------------------------------------------------------
// weight fp32 -> fp16 pairs
// ---------------------------------------------------------------------------
__global__ void cvt_h(const float* __restrict__ in, uint32_t* __restrict__ out, int n2)
{
    int i = blockIdx.x * 256 + threadIdx.x;
    if (i < n2) {
        float2 v = ((const float2*)in)[i];
        out[i] = f2h2(v.x, v.y);
    }
}

// ---------------------------------------------------------------------------
// LayerNorm -> fp16 out
// ---------------------------------------------------------------------------
__global__ __launch_bounds__(128) void ln_kernel(
    const float* __restrict__ x, const float* __restrict__ gamma,
    const float* __restrict__ beta, uint32_t* __restrict__ outh)
{
    int row = blockIdx.x;
    int t   = threadIdx.x;
    const float* xr = x + (size_t)row * DMODEL;
    float4 v = *(const float4*)(xr + t * 4);
    float s  = v.x + v.y + v.z + v.w;
    float ss = v.x * v.x + v.y * v.y + v.z * v.z + v.w * v.w;
#pragma unroll
    for (int m = 16; m; m >>= 1) {
        s  += __shfl_xor_sync(0xffffffffu, s,  m);
        ss += __shfl_xor_sync(0xffffffffu, ss, m);
    }
    __shared__ float red[8];
    if ((t & 31) == 0) { red[t >> 5] = s; red[4 + (t >> 5)] = ss; }
    __syncthreads();
    float tot  = red[0] + red[1] + red[2] + red[3];
    float tot2 = red[4] + red[5] + red[6] + red[7];
    float mu   = tot * (1.0f / DMODEL);
    float var  = tot2 * (1.0f / DMODEL) - mu * mu;
    float rstd = rsqrtf(var + 1e-6f);
    float4 g = *(const float4*)(gamma + t * 4);
    float4 b = *(const float4*)(beta  + t * 4);
    float ox = (v.x - mu) * rstd * g.x + b.x;
    float oy = (v.y - mu) * rstd * g.y + b.y;
    float oz = (v.z - mu) * rstd * g.z + b.z;
    float ow = (v.w - mu) * rstd * g.w + b.w;
    *(uint2*)(outh + (row * DMODEL + t * 4) / 2) =
        make_uint2(f2h2(ox, oy), f2h2(oz, ow));
}

// ---------------------------------------------------------------------------
// fp16 tensor-core GEMM (NT): C[M,N] = A[M,K=512] * B[N,K]^T (+bias)
// A, B are fp16 in gmem -> GLOAD is raw uint4 (no cvt). Double-buffered.
// HOUT: write fp16 pairs; else fp32 (+bias).
// ---------------------------------------------------------------------------
#define GS 20   // smem row stride in half2 words (16 data + 4 pad)

template <bool BIAS, bool HOUT>
__global__ __launch_bounds__(256, 2) void mm_h(
    const __half* __restrict__ A, const __half* __restrict__ Bw,
    const float* __restrict__ bias, void* __restrict__ C, int N)
{
    __shared__ uint32_t As[2][128][GS];
    __shared__ uint32_t Bs[2][128][GS];
    int t    = threadIdx.x;
    int m0   = blockIdx.y * 128, n0 = blockIdx.x * 128;
    int warp = t >> 5, lane = t & 31, g = lane >> 2, tq = lane & 3;
    int wm   = (warp >> 2) * 64, wn = (warp & 3) * 32;

    int lrow = t >> 2;        // 0..63 (and +64)
    int lk2  = t & 3;         // 8-half group within the 32-k tile
    const __half* Ag = A  + (size_t)(m0 + lrow) * GK + lk2 * 8;
    const __half* Bg = Bw + (size_t)(n0 + lrow) * GK + lk2 * 8;

    float acc[4][4][4];
#pragma unroll
    for (int i = 0; i < 4; i++)
#pragma unroll
        for (int j = 0; j < 4; j++)
#pragma unroll
            for (int r = 0; r < 4; r++) acc[i][j][r] = 0.f;

    uint4 pA0, pA1, pB0, pB1;
#define GLOAD(kt)                                                             \
    do {                                                                      \
        pA0 = *(const uint4*)(Ag + (kt) * 32);                                \
        pA1 = *(const uint4*)(Ag + (size_t)64 * GK + (kt) * 32);              \
        pB0 = *(const uint4*)(Bg + (kt) * 32);                                \
        pB1 = *(const uint4*)(Bg + (size_t)64 * GK + (kt) * 32);              \
    } while (0)
#define GSTASH(buf)                                                           \
    do {                                                                      \
        *(uint4*)&As[buf][lrow][lk2 * 4]      = pA0;                          \
        *(uint4*)&As[buf][lrow + 64][lk2 * 4] = pA1;                          \
        *(uint4*)&Bs[buf][lrow][lk2 * 4]      = pB0;                          \
        *(uint4*)&Bs[buf][lrow + 64][lk2 * 4] = pB1;                          \
    } while (0)

    GLOAD(0);
    GSTASH(0);
    __syncthreads();

    const int NT = GK / 32;   // 16
    for (int kt = 0; kt < NT; kt++) {
        int buf = kt & 1;
        if (kt + 1 < NT) GLOAD(kt + 1);
#pragma unroll
        for (int ks = 0; ks < 2; ks++) {
            int k0 = ks * 8;
            uint32_t af[4][4], bf[4][2];
#pragma unroll
            for (int mt = 0; mt < 4; mt++) {
                int r = wm + mt * 16 + g;
                af[mt][0] = As[buf][r][k0 + tq];
                af[mt][1] = As[buf][r + 8][k0 + tq];
                af[mt][2] = As[buf][r][k0 + tq + 4];
                af[mt][3] = As[buf][r + 8][k0 + tq + 4];
            }
#pragma unroll
            for (int nt = 0; nt < 4; nt++) {
                int r = wn + nt * 8 + g;
                bf[nt][0] = Bs[buf][r][k0 + tq];
                bf[nt][1] = Bs[buf][r][k0 + tq + 4];
            }
#pragma unroll
            for (int mt = 0; mt < 4; mt++)
#pragma unroll
                for (int nt = 0; nt < 4; nt++)
                    mma16(acc[mt][nt][0], acc[mt][nt][1], acc[mt][nt][2], acc[mt][nt][3],
                          af[mt][0], af[mt][1], af[mt][2], af[mt][3],
                          bf[nt][0], bf[nt][1]);
        }
        if (kt + 1 < NT) GSTASH(buf ^ 1);
        __syncthreads();
    }
#undef GLOAD
#undef GSTASH

#pragma unroll
    for (int mt = 0; mt < 4; mt++) {
#pragma unroll
        for (int nt = 0; nt < 4; nt++) {
            int row = m0 + wm + mt * 16 + g;
            int col = n0 + wn + nt * 8 + 2 * tq;
            if (HOUT) {
                uint32_t* Ch = (uint32_t*)C;
                Ch[((size_t)row * N + col) >> 1] =
                    f2h2(acc[mt][nt][0], acc[mt][nt][1]);
                Ch[((size_t)(row + 8) * N + col) >> 1] =
                    f2h2(acc[mt][nt][2], acc[mt][nt][3]);
            } else {
                float* Cf = (float*)C;
                float b0 = 0.f, b1 = 0.f;
                if (BIAS) { b0 = bias[col]; b1 = bias[col + 1]; }
                *(float2*)(Cf + (size_t)row * N + col) =
                    make_float2(acc[mt][nt][0] + b0, acc[mt][nt][1] + b1);
                *(float2*)(Cf + (size_t)(row + 8) * N + col) =
                    make_float2(acc[mt][nt][2] + b0, acc[mt][nt][3] + b1);
            }
        }
    }
}

// ---------------------------------------------------------------------------
// Flash attention, fp16 mma.sync, exp2-domain softmax, L via ones-column.
// CTA = 256 Q rows; 256 threads = 8 warps x 32 rows (2 m16 tiles).
// QKV input is fp16. Q pre-scaled by 0.125*log2(e) -> scores in log2 domain;
// P = ex2.approx.f16x2(s - M). L accumulated by an extra all-ones n8 V tile
// (b-frag constant 1.0h) so L is exactly consistent with fp16 P.
// ---------------------------------------------------------------------------
#define QS2 36
#define AROWS 256
#define ATTN_SMEM_WORDS (AROWS * QS2 + 2 * 64 * QS2 + 2 * 64 * QS2)

__global__ __launch_bounds__(256, 1) void attn_h(
    const __half* __restrict__ qkv, uint32_t* __restrict__ outh)
{
    extern __shared__ uint32_t smu[];
    uint32_t* QPu = smu;
    uint32_t* Ks  = smu + AROWS * QS2;
    uint32_t* Vs  = Ks + 2 * 64 * QS2;

    int t = threadIdx.x, warp = t >> 5, lane = t & 31, g = lane >> 2, tq = lane & 3;
    int bh = blockIdx.y, b = bh >> 3, h = bh & 7;
    int mb = blockIdx.x * AROWS;
    size_t seq0 = (size_t)b * SEQ;
    const __half* base  = qkv + seq0 * QKVDIM + h * DHEAD;
    const __half* kbase = base + DMODEL;
    const __half* vbase = base + 2 * DMODEL;

    int d4 = t & 15, r0 = t >> 4;

    // Stage Q scaled by 0.125*log2(e) (fp32 scale for precision)
    {
        const float sc = 0.125f * 1.44269504f;
#pragma unroll
        for (int j = 0; j < 16; j++) {
            int row = r0 + 16 * j;
            uint2 q2 = *(const uint2*)(base + (size_t)(mb + row) * QKVDIM + d4 * 4);
            float2 f0 = __half22float2(*(__half2*)&q2.x);
            float2 f1 = __half22float2(*(__half2*)&q2.y);
            *(uint2*)&QPu[row * QS2 + d4 * 2] =
                make_uint2(f2h2(f0.x * sc, f0.y * sc), f2h2(f1.x * sc, f1.y * sc));
        }
    }
    __syncthreads();

    uint32_t* Pwu = QPu + warp * 32 * QS2;
    uint32_t qf[2][4][4];
#pragma unroll
    for (int mt = 0; mt < 2; mt++)
#pragma unroll
        for (int ks = 0; ks < 4; ks++) {
            int rA = (mt * 16 + g) * QS2, rB = (mt * 16 + g + 8) * QS2;
            qf[mt][ks][0] = Pwu[rA + ks * 8 + tq];
            qf[mt][ks][1] = Pwu[rB + ks * 8 + tq];
            qf[mt][ks][2] = Pwu[rA + ks * 8 + tq + 4];
            qf[mt][ks][3] = Pwu[rB + ks * 8 + tq + 4];
        }

    // oacc[.][8][.] is the L (ones) column
    float oacc[2][9][4];
#pragma unroll
    for (int mt = 0; mt < 2; mt++)
#pragma unroll
        for (int nt = 0; nt < 9; nt++)
#pragma unroll
            for (int r = 0; r < 4; r++) oacc[mt][nt][r] = 0.f;
    float Mm[2][2];
#pragma unroll
    for (int mt = 0; mt < 2; mt++) { Mm[mt][0] = -1e30f; Mm[mt][1] = -1e30f; }

    const int NC = SEQ / 64;
    uint2 kh[4];
    uint32_t vh[8];

#define LDG_CHUNK(c)                                                          \
    do {                                                                      \
        size_t key = (size_t)((c) * 64 + r0);                                 \
        kh[0] = *(const uint2*)(kbase + (key +  0) * QKVDIM + d4 * 4);        \
        kh[1] = *(const uint2*)(kbase + (key + 16) * QKVDIM + d4 * 4);        \
        kh[2] = *(const uint2*)(kbase + (key + 32) * QKVDIM + d4 * 4);        \
        kh[3] = *(const uint2*)(kbase + (key + 48) * QKVDIM + d4 * 4);        \
        uint2 w0 = *(const uint2*)(vbase + (key +  0) * QKVDIM + d4 * 4);     \
        uint2 w1 = *(const uint2*)(vbase + (key + 16) * QKVDIM + d4 * 4);     \
        uint2 w2 = *(const uint2*)(vbase + (key + 32) * QKVDIM + d4 * 4);     \
        uint2 w3 = *(const uint2*)(vbase + (key + 48) * QKVDIM + d4 * 4);     \
        vh[0] = prmt(w0.x, w2.x, 0x5410); vh[1] = prmt(w0.x, w2.x, 0x7632);   \
        vh[2] = prmt(w0.y, w2.y, 0x5410); vh[3] = prmt(w0.y, w2.y, 0x7632);   \
        vh[4] = prmt(w1.x, w3.x, 0x5410); vh[5] = prmt(w1.x, w3.x, 0x7632);   \
        vh[6] = prmt(w1.y, w3.y, 0x5410); vh[7] = prmt(w1.y, w3.y, 0x7632);   \
    } while (0)

#define STS_CHUNK(p)                                                          \
    do {                                                                      \
        uint32_t* kb = Ks + (p) * 64 * QS2;                                   \
        uint32_t* vb = Vs + (p) * 64 * QS2;                                   \
        _Pragma("unroll")                                                     \
        for (int i = 0; i < 4; i++) {                                         \
            int r = r0 + 16 * i;                                              \
            int lam = ((r & 31) << 1) | (r >> 5);                             \
            *(uint2*)&kb[lam * QS2 + d4 * 2] = kh[i];                         \
        }                                                                     \
        _Pragma("unroll")                                                     \
        for (int k = 0; k < 4; k++) {                                         \
            int d = d4 * 4 + k;                                               \
            int sw = ((d >> 3) & 3) << 3;                                     \
            vb[d * QS2 + (r0 ^ sw)]        = vh[k];                           \
            vb[d * QS2 + ((r0 + 16) ^ sw)] = vh[4 + k];                       \
        }                                                                     \
    } while (0)

    LDG_CHUNK(0);
    STS_CHUNK(0);
    LDG_CHUNK(1);
    __syncthreads();

    const uint32_t ONE2 = 0x3C003C00u;   // half2(1.0, 1.0)

    for (int kc = 0; kc < NC; kc++) {
        int p = kc & 1;
        if (kc + 1 < NC) STS_CHUNK(p ^ 1);
        const uint32_t* Kb = Ks + p * 64 * QS2;
        const uint32_t* Vb = Vs + p * 64 * QS2;

        float sacc[2][8][4];
#pragma unroll
        for (int mt = 0; mt < 2; mt++)
#pragma unroll
            for (int nt = 0; nt < 8; nt++)
#pragma unroll
                for (int r = 0; r < 4; r++) sacc[mt][nt][r] = 0.f;

#pragma unroll
        for (int ks = 0; ks < 4; ks++) {
            int k0 = ks * 8;
#pragma unroll
            for (int nt = 0; nt < 8; nt++) {
                int kr = (nt * 8 + g) * QS2;
                uint32_t b0 = Kb[kr + k0 + tq];
                uint32_t b1 = Kb[kr + k0 + tq + 4];
                mma16(sacc[0][nt][0], sacc[0][nt][1], sacc[0][nt][2], sacc[0][nt][3],
                      qf[0][ks][0], qf[0][ks][1], qf[0][ks][2], qf[0][ks][3], b0, b1);
                mma16(sacc[1][nt][0], sacc[1][nt][1], sacc[1][nt][2], sacc[1][nt][3],
                      qf[1][ks][0], qf[1][ks][1], qf[1][ks][2], qf[1][ks][3], b0, b1);
            }
        }

        // Online softmax in log2 domain; P = ex2(s - M) as half2
#pragma unroll
        for (int mt = 0; mt < 2; mt++) {
            float cm0 = sacc[mt][0][0], cm1 = sacc[mt][0][2];
#pragma unroll
            for (int nt = 0; nt < 8; nt++) {
                cm0 = fmaxf(cm0, fmaxf(sacc[mt][nt][0], sacc[mt][nt][1]));
                cm1 = fmaxf(cm1, fmaxf(sacc[mt][nt][2], sacc[mt][nt][3]));
            }
            cm0 = fmaxf(cm0, __shfl_xor_sync(0xffffffffu, cm0, 1));
            cm0 = fmaxf(cm0, __shfl_xor_sync(0xffffffffu, cm0, 2));
            cm1 = fmaxf(cm1, __shfl_xor_sync(0xffffffffu, cm1, 1));
            cm1 = fmaxf(cm1, __shfl_xor_sync(0xffffffffu, cm1, 2));
            float nM0 = fmaxf(Mm[mt][0], cm0), nM1 = fmaxf(Mm[mt][1], cm1);
            float a0 = exp2f(Mm[mt][0] - nM0), a1 = exp2f(Mm[mt][1] - nM1);
            Mm[mt][0] = nM0; Mm[mt][1] = nM1;

#pragma unroll
            for (int nt = 0; nt < 9; nt++) {
                oacc[mt][nt][0] *= a0; oacc[mt][nt][1] *= a0;
                oacc[mt][nt][2] *= a1; oacc[mt][nt][3] *= a1;
            }
#pragma unroll
            for (int nt = 0; nt < 8; nt++) {
                uint32_t u0 = ex2h2(f2h2(sacc[mt][nt][0] - nM0,
                                         sacc[mt][nt][1] - nM0));
                uint32_t u1 = ex2h2(f2h2(sacc[mt][nt][2] - nM1,
                                         sacc[mt][nt][3] - nM1));
                Pwu[(mt * 16 + g) * QS2 + nt * 4 + tq]     = u0;
                Pwu[(mt * 16 + g + 8) * QS2 + nt * 4 + tq] = u1;
            }
        }
        __syncwarp();

        if (kc + 2 < NC) LDG_CHUNK(kc + 2);

        // O += P @ [V | 1]
#pragma unroll
        for (int ks = 0; ks < 4; ks++) {
            int k0 = ks * 8;
            uint32_t pa[2][4];
#pragma unroll
            for (int mt = 0; mt < 2; mt++) {
                pa[mt][0] = Pwu[(mt * 16 + g) * QS2 + k0 + tq];
                pa[mt][1] = Pwu[(mt * 16 + g + 8) * QS2 + k0 + tq];
                pa[mt][2] = Pwu[(mt * 16 + g) * QS2 + k0 + tq + 4];
                pa[mt][3] = Pwu[(mt * 16 + g + 8) * QS2 + k0 + tq + 4];
            }
#pragma unroll
            for (int nt = 0; nt < 8; nt++) {
                int sw = (nt & 3) << 3;
                int vr = (nt * 8 + g) * QS2;
                uint32_t b0 = Vb[vr + ((k0 + tq) ^ sw)];
                uint32_t b1 = Vb[vr + ((k0 + tq + 4) ^ sw)];
                mma16(oacc[0][nt][0], oacc[0][nt][1], oacc[0][nt][2], oacc[0][nt][3],
                      pa[0][0], pa[0][1], pa[0][2], pa[0][3], b0, b1);
                mma16(oacc[1][nt][0], oacc[1][nt][1], oacc[1][nt][2], oacc[1][nt][3],
                      pa[1][0], pa[1][1], pa[1][2], pa[1][3], b0, b1);
            }
            // L column (ones)
            mma16(oacc[0][8][0], oacc[0][8][1], oacc[0][8][2], oacc[0][8][3],
                  pa[0][0], pa[0][1], pa[0][2], pa[0][3], ONE2, ONE2);
            mma16(oacc[1][8][0], oacc[1][8][1], oacc[1][8][2], oacc[1][8][3],
                  pa[1][0], pa[1][1], pa[1][2], pa[1][3], ONE2, ONE2);
        }
        __syncthreads();
    }
#undef LDG_CHUNK
#undef STS_CHUNK

    // Normalize + pack fp16 pairs
#pragma unroll
    for (int mt = 0; mt < 2; mt++) {
        float i0 = 1.0f / oacc[mt][8][0], i1 = 1.0f / oacc[mt][8][2];
        int row0 = mb + warp * 32 + mt * 16 + g;
#pragma unroll
        for (int nt = 0; nt < 8; nt++) {
            int col = h * DHEAD + nt * 8 + 2 * tq;
            outh[((seq0 + row0) * DMODEL + col) >> 1] =
                f2h2(oacc[mt][nt][0] * i0, oacc[mt][nt][1] * i0);
            outh[((seq0 + row0 + 8) * DMODEL + col) >> 1] =
                f2h2(oacc[mt][nt][2] * i1, oacc[mt][nt][3] * i1);
        }
    }
}

// ---------------------------------------------------------------------------
extern "C" void kernel_launch(void* const* d_in, const int* in_sizes, int n_in,
                              void* d_out, int out_size)
{
    (void)in_sizes; (void)n_in; (void)out_size;
    const float* x      = (const float*)d_in[0];
    const float* w_qkv  = (const float*)d_in[1];
    const float* w_proj = (const float*)d_in[2];
    const float* b_proj = (const float*)d_in[3];
    const float* gamma  = (const float*)d_in[4];
    const float* beta   = (const float*)d_in[5];
    float* out = (float*)d_out;

    uint32_t *xnh, *qkvh, *atth, *wqh, *wph;
    cudaGetSymbolAddress((void**)&xnh,  g_xnh);
    cudaGetSymbolAddress((void**)&qkvh, g_qkvh);
    cudaGetSymbolAddress((void**)&atth, g_atth);
    cudaGetSymbolAddress((void**)&wqh,  g_wqkvh);
    cudaGetSymbolAddress((void**)&wph,  g_wprojh);

    const int SMEM = ATTN_SMEM_WORDS * 4;
    cudaFuncSetAttribute(attn_h,
                         cudaFuncAttributeMaxDynamicSharedMemorySize, SMEM);

    cvt_h<<<(QKVDIM * DMODEL / 2 + 255) / 256, 256>>>(w_qkv, wqh, QKVDIM * DMODEL / 2);
    cvt_h<<<(DMODEL * DMODEL / 2 + 255) / 256, 256>>>(w_proj, wph, DMODEL * DMODEL / 2);
    ln_kernel<<<ROWS, 128>>>(x, gamma, beta, xnh);
    mm_h<false, true><<<dim3(QKVDIM / 128, ROWS / 128), 256>>>(
        (const __half*)xnh, (const __half*)wqh, nullptr, qkvh, QKVDIM);
    attn_h<<<dim3(SEQ / AROWS, BATCH * NHEAD), 256, SMEM>>>(
        (const __half*)qkvh, atth);
    mm_h<true, false><<<dim3(DMODEL / 128, ROWS / 128), 256>>>(
        (const __half*)atth, (const __half*)wph, b_proj, out, DMODEL);
}

// round 11
// speedup vs baseline: 3.3325x; 1.0309x over previous
#include <cuda_runtime.h>
#include <cuda_fp16.h>
#include <cstdint>

#define BATCH  8
#define SEQ    2048
#define DMODEL 512
#define NHEAD  8
#define DHEAD  64
#define ROWS   (BATCH * SEQ)     // 16384
#define QKVDIM (3 * DMODEL)      // 1536
#define GK     512

// Scratch (allocation-free contract)
__device__ uint32_t g_xnh  [ROWS * DMODEL / 2];   // LN out, fp16 pairs
__device__ uint32_t g_qkvh [ROWS * QKVDIM / 2];   // QKV out, fp16 pairs
__device__ uint32_t g_atth [ROWS * DMODEL / 2];   // attn out, fp16 pairs
__device__ uint32_t g_wqkvh[QKVDIM * DMODEL / 2]; // fp16 weights
__device__ uint32_t g_wprojh[DMODEL * DMODEL / 2];

// ---------------------------------------------------------------------------
// helpers
// ---------------------------------------------------------------------------
__device__ __forceinline__ uint32_t f2h2(float lo, float hi) {
    uint32_t r;
    asm("cvt.rn.f16x2.f32 %0, %1, %2;" : "=r"(r) : "f"(hi), "f"(lo));
    return r;
}

__device__ __forceinline__ uint32_t prmt(uint32_t a, uint32_t b, uint32_t sel) {
    uint32_t d;
    asm("prmt.b32 %0, %1, %2, %3;" : "=r"(d) : "r"(a), "r"(b), "r"(sel));
    return d;
}

__device__ __forceinline__ uint32_t ex2h2(uint32_t x) {
    uint32_t r;
    asm("ex2.approx.f16x2 %0, %1;" : "=r"(r) : "r"(x));
    return r;
}

__device__ __forceinline__ void mma16(float& c0, float& c1, float& c2, float& c3,
                                      uint32_t a0, uint32_t a1, uint32_t a2, uint32_t a3,
                                      uint32_t b0, uint32_t b1) {
    asm volatile(
        "mma.sync.aligned.m16n8k16.row.col.f32.f16.f16.f32 "
        "{%0,%1,%2,%3}, {%4,%5,%6,%7}, {%8,%9}, {%0,%1,%2,%3};"
        : "+f"(c0), "+f"(c1), "+f"(c2), "+f"(c3)
        : "r"(a0), "r"(a1), "r"(a2), "r"(a3), "r"(b0), "r"(b1));
}

// ---------------------------------------------------------------------------
// weight fp32 -> fp16 pairs
// ---------------------------------------------------------------------------
__global__ void cvt_h(const float* __restrict__ in, uint32_t* __restrict__ out, int n2)
{
    int i = blockIdx.x * 256 + threadIdx.x;
    if (i < n2) {
        float2 v = ((const float2*)in)[i];
        out[i] = f2h2(v.x, v.y);
    }
}

// ---------------------------------------------------------------------------
// LayerNorm -> fp16 out
// ---------------------------------------------------------------------------
__global__ __launch_bounds__(128) void ln_kernel(
    const float* __restrict__ x, const float* __restrict__ gamma,
    const float* __restrict__ beta, uint32_t* __restrict__ outh)
{
    int row = blockIdx.x;
    int t   = threadIdx.x;
    const float* xr = x + (size_t)row * DMODEL;
    float4 v = *(const float4*)(xr + t * 4);
    float s  = v.x + v.y + v.z + v.w;
    float ss = v.x * v.x + v.y * v.y + v.z * v.z + v.w * v.w;
#pragma unroll
    for (int m = 16; m; m >>= 1) {
        s  += __shfl_xor_sync(0xffffffffu, s,  m);
        ss += __shfl_xor_sync(0xffffffffu, ss, m);
    }
    __shared__ float red[8];
    if ((t & 31) == 0) { red[t >> 5] = s; red[4 + (t >> 5)] = ss; }
    __syncthreads();
    float tot  = red[0] + red[1] + red[2] + red[3];
    float tot2 = red[4] + red[5] + red[6] + red[7];
    float mu   = tot * (1.0f / DMODEL);
    float var  = tot2 * (1.0f / DMODEL) - mu * mu;
    float rstd = rsqrtf(var + 1e-6f);
    float4 g = *(const float4*)(gamma + t * 4);
    float4 b = *(const float4*)(beta  + t * 4);
    float ox = (v.x - mu) * rstd * g.x + b.x;
    float oy = (v.y - mu) * rstd * g.y + b.y;
    float oz = (v.z - mu) * rstd * g.z + b.z;
    float ow = (v.w - mu) * rstd * g.w + b.w;
    *(uint2*)(outh + (row * DMODEL + t * 4) / 2) =
        make_uint2(f2h2(ox, oy), f2h2(oz, ow));
}

// ---------------------------------------------------------------------------
// fp16 tensor-core GEMM (NT): C[M,N] = A[M,K=512] * B[N,K]^T (+bias)
// (unchanged from measured-best R10 version)
// ---------------------------------------------------------------------------
#define GS 20   // smem row stride in half2 words (16 data + 4 pad)

template <bool BIAS, bool HOUT>
__global__ __launch_bounds__(256, 2) void mm_h(
    const __half* __restrict__ A, const __half* __restrict__ Bw,
    const float* __restrict__ bias, void* __restrict__ C, int N)
{
    __shared__ uint32_t As[2][128][GS];
    __shared__ uint32_t Bs[2][128][GS];
    int t    = threadIdx.x;
    int m0   = blockIdx.y * 128, n0 = blockIdx.x * 128;
    int warp = t >> 5, lane = t & 31, g = lane >> 2, tq = lane & 3;
    int wm   = (warp >> 2) * 64, wn = (warp & 3) * 32;

    int lrow = t >> 2;        // 0..63 (and +64)
    int lk2  = t & 3;         // 8-half group within the 32-k tile
    const __half* Ag = A  + (size_t)(m0 + lrow) * GK + lk2 * 8;
    const __half* Bg = Bw + (size_t)(n0 + lrow) * GK + lk2 * 8;

    float acc[4][4][4];
#pragma unroll
    for (int i = 0; i < 4; i++)
#pragma unroll
        for (int j = 0; j < 4; j++)
#pragma unroll
            for (int r = 0; r < 4; r++) acc[i][j][r] = 0.f;

    uint4 pA0, pA1, pB0, pB1;
#define GLOAD(kt)                                                             \
    do {                                                                      \
        pA0 = *(const uint4*)(Ag + (kt) * 32);                                \
        pA1 = *(const uint4*)(Ag + (size_t)64 * GK + (kt) * 32);              \
        pB0 = *(const uint4*)(Bg + (kt) * 32);                                \
        pB1 = *(const uint4*)(Bg + (size_t)64 * GK + (kt) * 32);              \
    } while (0)
#define GSTASH(buf)                                                           \
    do {                                                                      \
        *(uint4*)&As[buf][lrow][lk2 * 4]      = pA0;                          \
        *(uint4*)&As[buf][lrow + 64][lk2 * 4] = pA1;                          \
        *(uint4*)&Bs[buf][lrow][lk2 * 4]      = pB0;                          \
        *(uint4*)&Bs[buf][lrow + 64][lk2 * 4] = pB1;                          \
    } while (0)

    GLOAD(0);
    GSTASH(0);
    __syncthreads();

    const int NT = GK / 32;   // 16
    for (int kt = 0; kt < NT; kt++) {
        int buf = kt & 1;
        if (kt + 1 < NT) GLOAD(kt + 1);
#pragma unroll
        for (int ks = 0; ks < 2; ks++) {
            int k0 = ks * 8;
            uint32_t af[4][4], bf[4][2];
#pragma unroll
            for (int mt = 0; mt < 4; mt++) {
                int r = wm + mt * 16 + g;
                af[mt][0] = As[buf][r][k0 + tq];
                af[mt][1] = As[buf][r + 8][k0 + tq];
                af[mt][2] = As[buf][r][k0 + tq + 4];
                af[mt][3] = As[buf][r + 8][k0 + tq + 4];
            }
#pragma unroll
            for (int nt = 0; nt < 4; nt++) {
                int r = wn + nt * 8 + g;
                bf[nt][0] = Bs[buf][r][k0 + tq];
                bf[nt][1] = Bs[buf][r][k0 + tq + 4];
            }
#pragma unroll
            for (int mt = 0; mt < 4; mt++)
#pragma unroll
                for (int nt = 0; nt < 4; nt++)
                    mma16(acc[mt][nt][0], acc[mt][nt][1], acc[mt][nt][2], acc[mt][nt][3],
                          af[mt][0], af[mt][1], af[mt][2], af[mt][3],
                          bf[nt][0], bf[nt][1]);
        }
        if (kt + 1 < NT) GSTASH(buf ^ 1);
        __syncthreads();
    }
#undef GLOAD
#undef GSTASH

#pragma unroll
    for (int mt = 0; mt < 4; mt++) {
#pragma unroll
        for (int nt = 0; nt < 4; nt++) {
            int row = m0 + wm + mt * 16 + g;
            int col = n0 + wn + nt * 8 + 2 * tq;
            if (HOUT) {
                uint32_t* Ch = (uint32_t*)C;
                Ch[((size_t)row * N + col) >> 1] =
                    f2h2(acc[mt][nt][0], acc[mt][nt][1]);
                Ch[((size_t)(row + 8) * N + col) >> 1] =
                    f2h2(acc[mt][nt][2], acc[mt][nt][3]);
            } else {
                float* Cf = (float*)C;
                float b0 = 0.f, b1 = 0.f;
                if (BIAS) { b0 = bias[col]; b1 = bias[col + 1]; }
                *(float2*)(Cf + (size_t)row * N + col) =
                    make_float2(acc[mt][nt][0] + b0, acc[mt][nt][1] + b1);
                *(float2*)(Cf + (size_t)(row + 8) * N + col) =
                    make_float2(acc[mt][nt][2] + b0, acc[mt][nt][3] + b1);
            }
        }
    }
}

// ---------------------------------------------------------------------------
// Flash attention, fp16 mma.sync, exp2-domain softmax, L via ones-column,
// P KEPT IN REGISTERS: fp16 C-fragment layout (c0,c1)@(g,2tq) == A-fragment
// (a0)@(g,k=2tq) -> ex2h2 output words are directly the PV A-operands:
//   frag[ks] = { u0(nt=2ks), u1(nt=2ks), u0(nt=2ks+1), u1(nt=2ks+1) }.
// No P smem write/read, no __syncwarp.
// ---------------------------------------------------------------------------
#define QS2 36
#define AROWS 256
#define ATTN_SMEM_WORDS (AROWS * QS2 + 2 * 64 * QS2 + 2 * 64 * QS2)

__global__ __launch_bounds__(256, 1) void attn_h(
    const __half* __restrict__ qkv, uint32_t* __restrict__ outh)
{
    extern __shared__ uint32_t smu[];
    uint32_t* QPu = smu;                      // [256][36] Q staging
    uint32_t* Ks  = smu + AROWS * QS2;        // [2][64][36] logical-key-major
    uint32_t* Vs  = Ks + 2 * 64 * QS2;        // [2][64][36] d-major V^T

    int t = threadIdx.x, warp = t >> 5, lane = t & 31, g = lane >> 2, tq = lane & 3;
    int bh = blockIdx.y, b = bh >> 3, h = bh & 7;
    int mb = blockIdx.x * AROWS;
    size_t seq0 = (size_t)b * SEQ;
    const __half* base  = qkv + seq0 * QKVDIM + h * DHEAD;
    const __half* kbase = base + DMODEL;
    const __half* vbase = base + 2 * DMODEL;

    int d4 = t & 15, r0 = t >> 4;

    // Stage Q scaled by 0.125*log2(e) (fp32 scale for precision)
    {
        const float sc = 0.125f * 1.44269504f;
#pragma unroll
        for (int j = 0; j < 16; j++) {
            int row = r0 + 16 * j;
            uint2 q2 = *(const uint2*)(base + (size_t)(mb + row) * QKVDIM + d4 * 4);
            float2 f0 = __half22float2(*(__half2*)&q2.x);
            float2 f1 = __half22float2(*(__half2*)&q2.y);
            *(uint2*)&QPu[row * QS2 + d4 * 2] =
                make_uint2(f2h2(f0.x * sc, f0.y * sc), f2h2(f1.x * sc, f1.y * sc));
        }
    }
    __syncthreads();

    uint32_t* Qw = QPu + warp * 32 * QS2;
    uint32_t qf[2][4][4];
#pragma unroll
    for (int mt = 0; mt < 2; mt++)
#pragma unroll
        for (int ks = 0; ks < 4; ks++) {
            int rA = (mt * 16 + g) * QS2, rB = (mt * 16 + g + 8) * QS2;
            qf[mt][ks][0] = Qw[rA + ks * 8 + tq];
            qf[mt][ks][1] = Qw[rB + ks * 8 + tq];
            qf[mt][ks][2] = Qw[rA + ks * 8 + tq + 4];
            qf[mt][ks][3] = Qw[rB + ks * 8 + tq + 4];
        }

    // oacc[.][8][.] is the L (ones) column
    float oacc[2][9][4];
#pragma unroll
    for (int mt = 0; mt < 2; mt++)
#pragma unroll
        for (int nt = 0; nt < 9; nt++)
#pragma unroll
            for (int r = 0; r < 4; r++) oacc[mt][nt][r] = 0.f;
    float Mm[2][2];
#pragma unroll
    for (int mt = 0; mt < 2; mt++) { Mm[mt][0] = -1e30f; Mm[mt][1] = -1e30f; }

    const int NC = SEQ / 64;
    uint2 kh[4];
    uint32_t vh[8];

#define LDG_CHUNK(c)                                                          \
    do {                                                                      \
        size_t key = (size_t)((c) * 64 + r0);                                 \
        kh[0] = *(const uint2*)(kbase + (key +  0) * QKVDIM + d4 * 4);        \
        kh[1] = *(const uint2*)(kbase + (key + 16) * QKVDIM + d4 * 4);        \
        kh[2] = *(const uint2*)(kbase + (key + 32) * QKVDIM + d4 * 4);        \
        kh[3] = *(const uint2*)(kbase + (key + 48) * QKVDIM + d4 * 4);        \
        uint2 w0 = *(const uint2*)(vbase + (key +  0) * QKVDIM + d4 * 4);     \
        uint2 w1 = *(const uint2*)(vbase + (key + 16) * QKVDIM + d4 * 4);     \
        uint2 w2 = *(const uint2*)(vbase + (key + 32) * QKVDIM + d4 * 4);     \
        uint2 w3 = *(const uint2*)(vbase + (key + 48) * QKVDIM + d4 * 4);     \
        vh[0] = prmt(w0.x, w2.x, 0x5410); vh[1] = prmt(w0.x, w2.x, 0x7632);   \
        vh[2] = prmt(w0.y, w2.y, 0x5410); vh[3] = prmt(w0.y, w2.y, 0x7632);   \
        vh[4] = prmt(w1.x, w3.x, 0x5410); vh[5] = prmt(w1.x, w3.x, 0x7632);   \
        vh[6] = prmt(w1.y, w3.y, 0x5410); vh[7] = prmt(w1.y, w3.y, 0x7632);   \
    } while (0)

#define STS_CHUNK(p)                                                          \
    do {                                                                      \
        uint32_t* kb = Ks + (p) * 64 * QS2;                                   \
        uint32_t* vb = Vs + (p) * 64 * QS2;                                   \
        _Pragma("unroll")                                                     \
        for (int i = 0; i < 4; i++) {                                         \
            int r = r0 + 16 * i;                                              \
            int lam = ((r & 31) << 1) | (r >> 5);                             \
            *(uint2*)&kb[lam * QS2 + d4 * 2] = kh[i];                         \
        }                                                                     \
        _Pragma("unroll")                                                     \
        for (int k = 0; k < 4; k++) {                                         \
            int d = d4 * 4 + k;                                               \
            int sw = ((d >> 3) & 3) << 3;                                     \
            vb[d * QS2 + (r0 ^ sw)]        = vh[k];                           \
            vb[d * QS2 + ((r0 + 16) ^ sw)] = vh[4 + k];                       \
        }                                                                     \
    } while (0)

    LDG_CHUNK(0);
    STS_CHUNK(0);
    LDG_CHUNK(1);
    __syncthreads();

    const uint32_t ONE2 = 0x3C003C00u;   // half2(1.0, 1.0)

    for (int kc = 0; kc < NC; kc++) {
        int p = kc & 1;
        if (kc + 1 < NC) STS_CHUNK(p ^ 1);
        const uint32_t* Kb = Ks + p * 64 * QS2;
        const uint32_t* Vb = Vs + p * 64 * QS2;

        float sacc[2][8][4];
#pragma unroll
        for (int mt = 0; mt < 2; mt++)
#pragma unroll
            for (int nt = 0; nt < 8; nt++)
#pragma unroll
                for (int r = 0; r < 4; r++) sacc[mt][nt][r] = 0.f;

#pragma unroll
        for (int ks = 0; ks < 4; ks++) {
            int k0 = ks * 8;
#pragma unroll
            for (int nt = 0; nt < 8; nt++) {
                int kr = (nt * 8 + g) * QS2;
                uint32_t b0 = Kb[kr + k0 + tq];
                uint32_t b1 = Kb[kr + k0 + tq + 4];
                mma16(sacc[0][nt][0], sacc[0][nt][1], sacc[0][nt][2], sacc[0][nt][3],
                      qf[0][ks][0], qf[0][ks][1], qf[0][ks][2], qf[0][ks][3], b0, b1);
                mma16(sacc[1][nt][0], sacc[1][nt][1], sacc[1][nt][2], sacc[1][nt][3],
                      qf[1][ks][0], qf[1][ks][1], qf[1][ks][2], qf[1][ks][3], b0, b1);
            }
        }

        // Online softmax in log2 domain; P stays in registers as PV A-frags
        uint32_t pa[2][4][4];
#pragma unroll
        for (int mt = 0; mt < 2; mt++) {
            float cm0 = sacc[mt][0][0], cm1 = sacc[mt][0][2];
#pragma unroll
            for (int nt = 0; nt < 8; nt++) {
                cm0 = fmaxf(cm0, fmaxf(sacc[mt][nt][0], sacc[mt][nt][1]));
                cm1 = fmaxf(cm1, fmaxf(sacc[mt][nt][2], sacc[mt][nt][3]));
            }
            cm0 = fmaxf(cm0, __shfl_xor_sync(0xffffffffu, cm0, 1));
            cm0 = fmaxf(cm0, __shfl_xor_sync(0xffffffffu, cm0, 2));
            cm1 = fmaxf(cm1, __shfl_xor_sync(0xffffffffu, cm1, 1));
            cm1 = fmaxf(cm1, __shfl_xor_sync(0xffffffffu, cm1, 2));
            float nM0 = fmaxf(Mm[mt][0], cm0), nM1 = fmaxf(Mm[mt][1], cm1);
            float a0 = exp2f(Mm[mt][0] - nM0), a1 = exp2f(Mm[mt][1] - nM1);
            Mm[mt][0] = nM0; Mm[mt][1] = nM1;

#pragma unroll
            for (int nt = 0; nt < 9; nt++) {
                oacc[mt][nt][0] *= a0; oacc[mt][nt][1] *= a0;
                oacc[mt][nt][2] *= a1; oacc[mt][nt][3] *= a1;
            }
#pragma unroll
            for (int nt = 0; nt < 8; nt++) {
                uint32_t u0 = ex2h2(f2h2(sacc[mt][nt][0] - nM0,
                                         sacc[mt][nt][1] - nM0));
                uint32_t u1 = ex2h2(f2h2(sacc[mt][nt][2] - nM1,
                                         sacc[mt][nt][3] - nM1));
                pa[mt][nt >> 1][(nt & 1) << 1]       = u0;   // a0 / a2
                pa[mt][nt >> 1][((nt & 1) << 1) + 1] = u1;   // a1 / a3
            }
        }

        if (kc + 2 < NC) LDG_CHUNK(kc + 2);

        // O += P @ [V | 1]   (P fragments already in registers)
#pragma unroll
        for (int ks = 0; ks < 4; ks++) {
            int k0 = ks * 8;
#pragma unroll
            for (int nt = 0; nt < 8; nt++) {
                int sw = (nt & 3) << 3;
                int vr = (nt * 8 + g) * QS2;
                uint32_t b0 = Vb[vr + ((k0 + tq) ^ sw)];
                uint32_t b1 = Vb[vr + ((k0 + tq + 4) ^ sw)];
                mma16(oacc[0][nt][0], oacc[0][nt][1], oacc[0][nt][2], oacc[0][nt][3],
                      pa[0][ks][0], pa[0][ks][1], pa[0][ks][2], pa[0][ks][3], b0, b1);
                mma16(oacc[1][nt][0], oacc[1][nt][1], oacc[1][nt][2], oacc[1][nt][3],
                      pa[1][ks][0], pa[1][ks][1], pa[1][ks][2], pa[1][ks][3], b0, b1);
            }
            // L column (ones)
            mma16(oacc[0][8][0], oacc[0][8][1], oacc[0][8][2], oacc[0][8][3],
                  pa[0][ks][0], pa[0][ks][1], pa[0][ks][2], pa[0][ks][3], ONE2, ONE2);
            mma16(oacc[1][8][0], oacc[1][8][1], oacc[1][8][2], oacc[1][8][3],
                  pa[1][ks][0], pa[1][ks][1], pa[1][ks][2], pa[1][ks][3], ONE2, ONE2);
        }
        __syncthreads();
    }
#undef LDG_CHUNK
#undef STS_CHUNK

    // Normalize + pack fp16 pairs
#pragma unroll
    for (int mt = 0; mt < 2; mt++) {
        float i0 = 1.0f / oacc[mt][8][0], i1 = 1.0f / oacc[mt][8][2];
        int row0 = mb + warp * 32 + mt * 16 + g;
#pragma unroll
        for (int nt = 0; nt < 8; nt++) {
            int col = h * DHEAD + nt * 8 + 2 * tq;
            outh[((seq0 + row0) * DMODEL + col) >> 1] =
                f2h2(oacc[mt][nt][0] * i0, oacc[mt][nt][1] * i0);
            outh[((seq0 + row0 + 8) * DMODEL + col) >> 1] =
                f2h2(oacc[mt][nt][2] * i1, oacc[mt][nt][3] * i1);
        }
    }
}

// ---------------------------------------------------------------------------
extern "C" void kernel_launch(void* const* d_in, const int* in_sizes, int n_in,
                              void* d_out, int out_size)
{
    (void)in_sizes; (void)n_in; (void)out_size;
    const float* x      = (const float*)d_in[0];
    const float* w_qkv  = (const float*)d_in[1];
    const float* w_proj = (const float*)d_in[2];
    const float* b_proj = (const float*)d_in[3];
    const float* gamma  = (const float*)d_in[4];
    const float* beta   = (const float*)d_in[5];
    float* out = (float*)d_out;

    uint32_t *xnh, *qkvh, *atth, *wqh, *wph;
    cudaGetSymbolAddress((void**)&xnh,  g_xnh);
    cudaGetSymbolAddress((void**)&qkvh, g_qkvh);
    cudaGetSymbolAddress((void**)&atth, g_atth);
    cudaGetSymbolAddress((void**)&wqh,  g_wqkvh);
    cudaGetSymbolAddress((void**)&wph,  g_wprojh);

    const int SMEM = ATTN_SMEM_WORDS * 4;
    cudaFuncSetAttribute(attn_h,
                         cudaFuncAttributeMaxDynamicSharedMemorySize, SMEM);

    cvt_h<<<(QKVDIM * DMODEL / 2 + 255) / 256, 256>>>(w_qkv, wqh, QKVDIM * DMODEL / 2);
    cvt_h<<<(DMODEL * DMODEL / 2 + 255) / 256, 256>>>(w_proj, wph, DMODEL * DMODEL / 2);
    ln_kernel<<<ROWS, 128>>>(x, gamma, beta, xnh);
    mm_h<false, true><<<dim3(QKVDIM / 128, ROWS / 128), 256>>>(
        (const __half*)xnh, (const __half*)wqh, nullptr, qkvh, QKVDIM);
    attn_h<<<dim3(SEQ / AROWS, BATCH * NHEAD), 256, SMEM>>>(
        (const __half*)qkvh, atth);
    mm_h<true, false><<<dim3(DMODEL / 128, ROWS / 128), 256>>>(
        (const __half*)atth, (const __half*)wph, b_proj, out, DMODEL);
}